// round 1
// baseline (speedup 1.0000x reference)
#include <cuda_runtime.h>
#include <math.h>

#define B_ 2
#define T_ 2048
#define M_ 1024
#define H_ 8
#define D_ 128
#define BH_ (B_*H_)

// Scratch (allocation-free: device globals)
__device__ float g_q[BH_ * T_ * D_];          // [B,H,T,D]
__device__ float g_k[BH_ * T_ * D_];          // [B,H,T,D]
__device__ float g_v[BH_ * T_ * D_];          // [B,H,T,D]
__device__ float g_o[B_ * T_ * H_ * D_];      // [B,T,H*D]

// ---------------------------------------------------------------------------
// GEMM: 128x128 tile, 256 threads, 8x8 microtile, K-chunk 16.
// MODE 0: C = X[4096,1024] * W{q,k,v}[1024,1024] (z selects), scatter-store
//         into g_q/g_k/g_v laid out [B,H,T,D].
// MODE 1: C = g_o[4096,1024] * W0[1024,1024], plain row-major store to Cout.
// ---------------------------------------------------------------------------
template <int MODE>
__global__ void __launch_bounds__(256) gemm_kernel(
    const float* __restrict__ A,
    const float* __restrict__ W0,
    const float* __restrict__ W1,
    const float* __restrict__ W2,
    float* __restrict__ Cout)
{
    __shared__ float As[16][132];   // transposed A tile: As[kk][r]
    __shared__ float Bs[16][128];   // Bs[kk][c]

    const int bx = blockIdx.x;      // N tile (cols), 0..7
    const int by = blockIdx.y;      // M tile (rows), 0..31

    const float* W;
    float* O;
    if (MODE == 0) {
        W = (blockIdx.z == 0) ? W0 : (blockIdx.z == 1) ? W1 : W2;
        O = (blockIdx.z == 0) ? g_q : (blockIdx.z == 1) ? g_k : g_v;
    } else {
        W = W0;
        O = Cout;
    }
    const float* Ap = (MODE == 0) ? A : g_o;

    const int tid = threadIdx.x;
    const int ty = tid >> 4, tx = tid & 15;
    const int r0 = by * 128, c0 = bx * 128;

    float acc[8][8];
#pragma unroll
    for (int i = 0; i < 8; i++)
#pragma unroll
        for (int j = 0; j < 8; j++) acc[i][j] = 0.0f;

    for (int k0 = 0; k0 < 1024; k0 += 16) {
        // Load A tile (128 rows x 16 k), store transposed
#pragma unroll
        for (int i = 0; i < 2; i++) {
            int f = tid + i * 256;           // 0..511 float4s
            int r = f >> 2, k4 = f & 3;
            float4 a = *(const float4*)(Ap + (size_t)(r0 + r) * 1024 + k0 + 4 * k4);
            As[4 * k4 + 0][r] = a.x;
            As[4 * k4 + 1][r] = a.y;
            As[4 * k4 + 2][r] = a.z;
            As[4 * k4 + 3][r] = a.w;
        }
        // Load B tile (16 k x 128 cols)
#pragma unroll
        for (int i = 0; i < 2; i++) {
            int f = tid + i * 256;
            int kk = f >> 5, c4 = f & 31;
            *(float4*)&Bs[kk][4 * c4] =
                *(const float4*)(W + (size_t)(k0 + kk) * 1024 + c0 + 4 * c4);
        }
        __syncthreads();

#pragma unroll
        for (int kk = 0; kk < 16; kk++) {
            float a[8], b[8];
            *(float4*)&a[0] = *(float4*)&As[kk][8 * ty];
            *(float4*)&a[4] = *(float4*)&As[kk][8 * ty + 4];
            *(float4*)&b[0] = *(float4*)&Bs[kk][8 * tx];
            *(float4*)&b[4] = *(float4*)&Bs[kk][8 * tx + 4];
#pragma unroll
            for (int i = 0; i < 8; i++)
#pragma unroll
                for (int j = 0; j < 8; j++)
                    acc[i][j] = fmaf(a[i], b[j], acc[i][j]);
        }
        __syncthreads();
    }

    // Store
#pragma unroll
    for (int i = 0; i < 8; i++) {
        int r = r0 + 8 * ty + i;
        float* dst;
        if (MODE == 0) {
            int bb = r >> 11;        // r / 2048
            int t  = r & 2047;
            // col block bx == head h (128 cols per head); d = 8*tx + e
            dst = O + ((size_t)(bb * H_ + bx) * T_ + t) * D_ + 8 * tx;
        } else {
            dst = O + (size_t)r * 1024 + c0 + 8 * tx;
        }
        *(float4*)dst       = make_float4(acc[i][0], acc[i][1], acc[i][2], acc[i][3]);
        *(float4*)(dst + 4) = make_float4(acc[i][4], acc[i][5], acc[i][6], acc[i][7]);
    }
}

// ---------------------------------------------------------------------------
// Fractional RoPE, in-place on g_q/g_k.
// rot part = first 64 dims; half = 32. pair (d, d+32), d in [0,32).
// grid (T, B*H), 64 threads: tid<32 -> q, tid>=32 -> k.
// ---------------------------------------------------------------------------
__global__ void rope_kernel()
{
    const int t  = blockIdx.x;
    const int bh = blockIdx.y;
    const int d  = threadIdx.x & 31;
    float* base = ((threadIdx.x < 32) ? g_q : g_k) + ((size_t)bh * T_ + t) * D_;

    float freq = powf(10000.0f, -(float)d * (1.0f / 32.0f));
    float rad  = (float)t * freq;
    float sn, cs;
    sincosf(rad, &sn, &cs);
    float e = base[d], o = base[d + 32];
    base[d]      = e * cs - o * sn;
    base[d + 32] = e * sn + o * cs;
}

// ---------------------------------------------------------------------------
// Flash attention (causal, scale 1/128), fp32 SIMT.
// Br = Bc = 64, 256 threads (16x16), 4x4 S microtile, 4x8 O microtile.
// Q,K staged d-major (transposed) in smem; V row-major; P via smem.
// grid (T/64, B*H). Output to g_o in [B,T,H*D].
// ---------------------------------------------------------------------------
__global__ void __launch_bounds__(256) attn_kernel()
{
    extern __shared__ float sm[];
    float* Qt = sm;                   // [128][64]  (d-major)
    float* Kt = Qt + 128 * 64;        // [128][64]
    float* Vs = Kt + 128 * 64;        // [64][128]
    float* Ps = Vs + 64 * 128;        // [64][68]   (pitch 68: 16B-aligned rows)

    const int qblk = blockIdx.x;
    const int bh   = blockIdx.y;
    const float* Qg = g_q + (size_t)bh * T_ * D_;
    const float* Kg = g_k + (size_t)bh * T_ * D_;
    const float* Vg = g_v + (size_t)bh * T_ * D_;

    const int tid = threadIdx.x;
    const int ty = tid >> 4, tx = tid & 15;

    // Load Q tile transposed: lane varies r -> conflict-free STS (pitch 64)
#pragma unroll
    for (int i = 0; i < 8; i++) {
        int f  = tid + i * 256;       // 0..2047 float4s
        int d4 = f >> 6;              // 0..31
        int r  = f & 63;              // 0..63
        float4 v = *(const float4*)(Qg + (size_t)(qblk * 64 + r) * D_ + 4 * d4);
        Qt[(4 * d4 + 0) * 64 + r] = v.x;
        Qt[(4 * d4 + 1) * 64 + r] = v.y;
        Qt[(4 * d4 + 2) * 64 + r] = v.z;
        Qt[(4 * d4 + 3) * 64 + r] = v.w;
    }

    float m[4], l[4], acc[4][8];
#pragma unroll
    for (int i = 0; i < 4; i++) {
        m[i] = -1e30f;
        l[i] = 0.0f;
#pragma unroll
        for (int e = 0; e < 8; e++) acc[i][e] = 0.0f;
    }

    for (int jt = 0; jt <= qblk; jt++) {
        __syncthreads();   // previous PV done before overwriting Kt/Vs

        // K transposed, V row-major
#pragma unroll
        for (int i = 0; i < 8; i++) {
            int f  = tid + i * 256;
            int d4 = f >> 6;
            int r  = f & 63;
            float4 kv = *(const float4*)(Kg + (size_t)(jt * 64 + r) * D_ + 4 * d4);
            Kt[(4 * d4 + 0) * 64 + r] = kv.x;
            Kt[(4 * d4 + 1) * 64 + r] = kv.y;
            Kt[(4 * d4 + 2) * 64 + r] = kv.z;
            Kt[(4 * d4 + 3) * 64 + r] = kv.w;
        }
#pragma unroll
        for (int i = 0; i < 8; i++) {
            int f  = tid + i * 256;
            int r  = f >> 5;          // 0..63
            int d4 = f & 31;
            *(float4*)&Vs[r * 128 + 4 * d4] =
                *(const float4*)(Vg + (size_t)(jt * 64 + r) * D_ + 4 * d4);
        }
        __syncthreads();

        // S = Q K^T
        float s[4][4];
#pragma unroll
        for (int i = 0; i < 4; i++)
#pragma unroll
            for (int j = 0; j < 4; j++) s[i][j] = 0.0f;

#pragma unroll 8
        for (int d = 0; d < 128; d++) {
            float qa[4], ka[4];
            *(float4*)qa = *(float4*)&Qt[d * 64 + 4 * ty];
            *(float4*)ka = *(float4*)&Kt[d * 64 + 4 * tx];
#pragma unroll
            for (int i = 0; i < 4; i++)
#pragma unroll
                for (int j = 0; j < 4; j++)
                    s[i][j] = fmaf(qa[i], ka[j], s[i][j]);
        }

        // scale + causal mask (only diagonal tile needs it)
        const float inv = 1.0f / 128.0f;
        const bool diag = (jt == qblk);
#pragma unroll
        for (int i = 0; i < 4; i++) {
            int ql = 4 * ty + i;
#pragma unroll
            for (int j = 0; j < 4; j++) {
                float val = s[i][j] * inv;
                if (diag && (ql < 4 * tx + j)) val = -1e30f;
                s[i][j] = val;
            }
        }

        // online softmax per row (row group = half-warp, width 16)
#pragma unroll
        for (int i = 0; i < 4; i++) {
            float tm = fmaxf(fmaxf(s[i][0], s[i][1]), fmaxf(s[i][2], s[i][3]));
#pragma unroll
            for (int off = 8; off > 0; off >>= 1)
                tm = fmaxf(tm, __shfl_xor_sync(0xffffffffu, tm, off, 16));
            float mn = fmaxf(m[i], tm);
            float al = expf(m[i] - mn);
            m[i] = mn;
            float rs = 0.0f;
#pragma unroll
            for (int j = 0; j < 4; j++) {
                float p = expf(s[i][j] - mn);
                s[i][j] = p;
                rs += p;
            }
#pragma unroll
            for (int off = 8; off > 0; off >>= 1)
                rs += __shfl_xor_sync(0xffffffffu, rs, off, 16);
            l[i] = l[i] * al + rs;
#pragma unroll
            for (int e = 0; e < 8; e++) acc[i][e] *= al;
            *(float4*)&Ps[(4 * ty + i) * 68 + 4 * tx] =
                make_float4(s[i][0], s[i][1], s[i][2], s[i][3]);
        }
        __syncthreads();

        // O += P @ V
#pragma unroll 2
        for (int c = 0; c < 64; c++) {
            float pf[4];
#pragma unroll
            for (int i = 0; i < 4; i++) pf[i] = Ps[(4 * ty + i) * 68 + c];
            float vf[8];
            *(float4*)&vf[0] = *(float4*)&Vs[c * 128 + 8 * tx];
            *(float4*)&vf[4] = *(float4*)&Vs[c * 128 + 8 * tx + 4];
#pragma unroll
            for (int i = 0; i < 4; i++)
#pragma unroll
                for (int e = 0; e < 8; e++)
                    acc[i][e] = fmaf(pf[i], vf[e], acc[i][e]);
        }
    }

    // epilogue: normalize and write O in [B,T,H*D]
    const int b = bh >> 3, h = bh & 7;
#pragma unroll
    for (int i = 0; i < 4; i++) {
        float invl = 1.0f / l[i];
        int t = qblk * 64 + 4 * ty + i;
        float* dst = g_o + ((size_t)(b * T_ + t) * H_ + h) * D_ + 8 * tx;
        *(float4*)dst = make_float4(acc[i][0] * invl, acc[i][1] * invl,
                                    acc[i][2] * invl, acc[i][3] * invl);
        *(float4*)(dst + 4) = make_float4(acc[i][4] * invl, acc[i][5] * invl,
                                          acc[i][6] * invl, acc[i][7] * invl);
    }
}

// ---------------------------------------------------------------------------
extern "C" void kernel_launch(void* const* d_in, const int* in_sizes, int n_in,
                              void* d_out, int out_size)
{
    const float* x  = (const float*)d_in[0];
    const float* wq = (const float*)d_in[1];
    const float* wk = (const float*)d_in[2];
    const float* wv = (const float*)d_in[3];
    const float* wo = (const float*)d_in[4];
    float* out = (float*)d_out;

    // QKV projection
    gemm_kernel<0><<<dim3(8, 32, 3), 256>>>(x, wq, wk, wv, nullptr);

    // Fractional RoPE on q, k
    rope_kernel<<<dim3(T_, BH_), 64>>>();

    // Flash attention
    const int smem_bytes = (128 * 64 * 2 + 64 * 128 + 64 * 68) * (int)sizeof(float);
    cudaFuncSetAttribute(attn_kernel,
                         cudaFuncAttributeMaxDynamicSharedMemorySize, smem_bytes);
    attn_kernel<<<dim3(T_ / 64, BH_), 256, smem_bytes>>>();

    // Output projection
    gemm_kernel<1><<<dim3(8, 32), 256>>>(nullptr, wo, nullptr, nullptr, out);
}

// round 4
// speedup vs baseline: 1.4857x; 1.4857x over previous
#include <cuda_runtime.h>
#include <cstdint>
#include <math.h>

#define B_ 2
#define T_ 2048
#define M_ 1024
#define H_ 8
#define D_ 128
#define BH_ (B_*H_)

// Scratch (allocation-free: device globals)
__device__ float g_q[BH_ * T_ * D_];          // [B,H,T,D]
__device__ float g_k[BH_ * T_ * D_];          // [B,H,T,D]
__device__ float g_v[BH_ * T_ * D_];          // [B,H,T,D]
__device__ float g_o[B_ * T_ * H_ * D_];      // [B,T,H*D]

__device__ __forceinline__ uint32_t f2tf(float x) {
    uint32_t r;
    asm("cvt.rna.tf32.f32 %0, %1;" : "=r"(r) : "f"(x));
    return r;
}

__device__ __forceinline__ void mma_tf32(float c[4], const uint32_t a[4],
                                         const uint32_t b[2]) {
    asm volatile(
        "mma.sync.aligned.m16n8k8.row.col.f32.tf32.tf32.f32 "
        "{%0,%1,%2,%3}, {%4,%5,%6,%7}, {%8,%9}, {%0,%1,%2,%3};"
        : "+f"(c[0]), "+f"(c[1]), "+f"(c[2]), "+f"(c[3])
        : "r"(a[0]), "r"(a[1]), "r"(a[2]), "r"(a[3]), "r"(b[0]), "r"(b[1]));
}

// ---------------------------------------------------------------------------
// tf32 mma.sync GEMM: C[4096,1024] = A[4096,1024] * W[1024,1024] (W is [k][n])
// 128x128 CTA tile, 8 warps (2m x 4n), warp tile 64x32, K-chunk 32,
// double-buffered dynamic smem, reg-staged global prefetch.
// MODE 0: A = x, W = wq/wk/wv (blockIdx.z), scatter into g_q/g_k/g_v [B,H,T,D].
// MODE 1: A = g_o, W = wo, row-major store to Cout.
// ---------------------------------------------------------------------------
#define AP 36    // As pitch (uint32)  : frag-load bank = 4g+lq  (conflict-free)
#define BP 136   // Bs pitch (uint32)  : frag-load bank = 8lq+g  (conflict-free)
#define AS_WORDS (128 * AP)           // 4608
#define BS_WORDS (32 * BP)            // 4352
#define GEMM_SMEM_BYTES ((2 * AS_WORDS + 2 * BS_WORDS) * 4)   // 71680

template <int MODE>
__global__ void __launch_bounds__(256) gemm_mma(
    const float* __restrict__ Ain,
    const float* __restrict__ W0,
    const float* __restrict__ W1,
    const float* __restrict__ W2,
    float* __restrict__ Cout)
{
    extern __shared__ uint32_t smw[];
    uint32_t* As[2] = { smw, smw + AS_WORDS };
    uint32_t* Bs[2] = { smw + 2 * AS_WORDS, smw + 2 * AS_WORDS + BS_WORDS };

    const float* Ap;
    const float* W;
    float* O;
    if (MODE == 0) {
        Ap = Ain;
        W = (blockIdx.z == 0) ? W0 : (blockIdx.z == 1) ? W1 : W2;
        O = (blockIdx.z == 0) ? g_q : (blockIdx.z == 1) ? g_k : g_v;
    } else {
        Ap = g_o;
        W = W0;
        O = Cout;
    }

    const int tid  = threadIdx.x;
    const int lane = tid & 31;
    const int wid  = tid >> 5;
    const int wm   = wid & 1;        // 0..1  (m)
    const int wn   = wid >> 1;       // 0..3  (n)
    const int g    = lane >> 2;      // group 0..7
    const int lq   = lane & 3;       // 0..3

    const int r0 = blockIdx.y * 128;
    const int c0 = blockIdx.x * 128;

    // Per-thread loader coords (A: 1024 f4/chunk, B: 1024 f4/chunk; 4 iters)
    float acc[4][4][4];
#pragma unroll
    for (int i = 0; i < 4; i++)
#pragma unroll
        for (int j = 0; j < 4; j++)
#pragma unroll
            for (int e = 0; e < 4; e++) acc[i][j][e] = 0.0f;

    float4 ra[4], rb[4];

    auto stage = [&](int buf) {
#pragma unroll
        for (int it = 0; it < 4; it++) {
            int idx = tid + it * 256;
            int r = idx >> 3, k4 = idx & 7;
            uint4 va = make_uint4(f2tf(ra[it].x), f2tf(ra[it].y),
                                  f2tf(ra[it].z), f2tf(ra[it].w));
            *(uint4*)&As[buf][r * AP + 4 * k4] = va;
            int k = idx >> 5, n4 = idx & 31;
            uint4 vb = make_uint4(f2tf(rb[it].x), f2tf(rb[it].y),
                                  f2tf(rb[it].z), f2tf(rb[it].w));
            *(uint4*)&Bs[buf][k * BP + 4 * n4] = vb;
        }
    };

    // ---- prologue: load + stage chunk 0 ----
#pragma unroll
    for (int it = 0; it < 4; it++) {
        int idx = tid + it * 256;
        int r = idx >> 3, k4 = idx & 7;
        ra[it] = *(const float4*)(Ap + (size_t)(r0 + r) * 1024 + 4 * k4);
        int k = idx >> 5, n4 = idx & 31;
        rb[it] = *(const float4*)(W + (size_t)k * 1024 + c0 + 4 * n4);
    }
    stage(0);
    __syncthreads();

    for (int c = 0; c < 32; c++) {
        const int buf = c & 1;

        // prefetch next chunk into regs
        if (c < 31) {
            const int kc = (c + 1) * 32;
#pragma unroll
            for (int it = 0; it < 4; it++) {
                int idx = tid + it * 256;
                int r = idx >> 3, k4 = idx & 7;
                ra[it] = *(const float4*)(Ap + (size_t)(r0 + r) * 1024 + kc + 4 * k4);
                int k = idx >> 5, n4 = idx & 31;
                rb[it] = *(const float4*)(W + (size_t)(kc + k) * 1024 + c0 + 4 * n4);
            }
        }

        // compute on buf
#pragma unroll
        for (int ks = 0; ks < 4; ks++) {
            const int kk = ks * 8;
            uint32_t afr[4][4];
#pragma unroll
            for (int mf = 0; mf < 4; mf++) {
                const uint32_t* p = &As[buf][(wm * 64 + mf * 16 + g) * AP + kk + lq];
                afr[mf][0] = p[0];
                afr[mf][1] = p[8 * AP];
                afr[mf][2] = p[4];
                afr[mf][3] = p[8 * AP + 4];
            }
            uint32_t bfr[4][2];
#pragma unroll
            for (int nf = 0; nf < 4; nf++) {
                const uint32_t* p = &Bs[buf][(kk + lq) * BP + wn * 32 + nf * 8 + g];
                bfr[nf][0] = p[0];
                bfr[nf][1] = p[4 * BP];
            }
#pragma unroll
            for (int mf = 0; mf < 4; mf++)
#pragma unroll
                for (int nf = 0; nf < 4; nf++)
                    mma_tf32(acc[mf][nf], afr[mf], bfr[nf]);
        }
        __syncthreads();

        if (c < 31) {
            stage(buf ^ 1);
            __syncthreads();
        }
    }

    // ---- epilogue ----
#pragma unroll
    for (int mf = 0; mf < 4; mf++) {
#pragma unroll
        for (int half = 0; half < 2; half++) {
            int row = r0 + wm * 64 + mf * 16 + g + half * 8;
            float* dst;
            if (MODE == 0) {
                int bb = row >> 11, t = row & 2047;
                dst = O + ((size_t)(bb * H_ + blockIdx.x) * T_ + t) * D_;
            } else {
                dst = O + (size_t)row * 1024 + c0;
            }
#pragma unroll
            for (int nf = 0; nf < 4; nf++) {
                int col = wn * 32 + nf * 8 + 2 * lq;
                float2 v = half ? make_float2(acc[mf][nf][2], acc[mf][nf][3])
                                : make_float2(acc[mf][nf][0], acc[mf][nf][1]);
                *(float2*)(dst + col) = v;
            }
        }
    }
}

// ---------------------------------------------------------------------------
// Fractional RoPE, in-place on g_q/g_k.
// ---------------------------------------------------------------------------
__global__ void rope_kernel()
{
    const int t  = blockIdx.x;
    const int bh = blockIdx.y;
    const int d  = threadIdx.x & 31;
    float* base = ((threadIdx.x < 32) ? g_q : g_k) + ((size_t)bh * T_ + t) * D_;

    float freq = powf(10000.0f, -(float)d * (1.0f / 32.0f));
    float rad  = (float)t * freq;
    float sn, cs;
    sincosf(rad, &sn, &cs);
    float e = base[d], o = base[d + 32];
    base[d]      = e * cs - o * sn;
    base[d + 32] = e * sn + o * cs;
}

// ---------------------------------------------------------------------------
// Flash attention (causal, scale 1/128), fp32 SIMT, __expf softmax.
// ---------------------------------------------------------------------------
__global__ void __launch_bounds__(256) attn_kernel()
{
    extern __shared__ float sm[];
    float* Qt = sm;                   // [128][64]  (d-major)
    float* Kt = Qt + 128 * 64;        // [128][64]
    float* Vs = Kt + 128 * 64;        // [64][128]
    float* Ps = Vs + 64 * 128;        // [64][68]

    const int qblk = blockIdx.x;
    const int bh   = blockIdx.y;
    const float* Qg = g_q + (size_t)bh * T_ * D_;
    const float* Kg = g_k + (size_t)bh * T_ * D_;
    const float* Vg = g_v + (size_t)bh * T_ * D_;

    const int tid = threadIdx.x;
    const int ty = tid >> 4, tx = tid & 15;

#pragma unroll
    for (int i = 0; i < 8; i++) {
        int f  = tid + i * 256;
        int d4 = f >> 6;
        int r  = f & 63;
        float4 v = *(const float4*)(Qg + (size_t)(qblk * 64 + r) * D_ + 4 * d4);
        Qt[(4 * d4 + 0) * 64 + r] = v.x;
        Qt[(4 * d4 + 1) * 64 + r] = v.y;
        Qt[(4 * d4 + 2) * 64 + r] = v.z;
        Qt[(4 * d4 + 3) * 64 + r] = v.w;
    }

    float m[4], l[4], acc[4][8];
#pragma unroll
    for (int i = 0; i < 4; i++) {
        m[i] = -1e30f;
        l[i] = 0.0f;
#pragma unroll
        for (int e = 0; e < 8; e++) acc[i][e] = 0.0f;
    }

    for (int jt = 0; jt <= qblk; jt++) {
        __syncthreads();

#pragma unroll
        for (int i = 0; i < 8; i++) {
            int f  = tid + i * 256;
            int d4 = f >> 6;
            int r  = f & 63;
            float4 kv = *(const float4*)(Kg + (size_t)(jt * 64 + r) * D_ + 4 * d4);
            Kt[(4 * d4 + 0) * 64 + r] = kv.x;
            Kt[(4 * d4 + 1) * 64 + r] = kv.y;
            Kt[(4 * d4 + 2) * 64 + r] = kv.z;
            Kt[(4 * d4 + 3) * 64 + r] = kv.w;
        }
#pragma unroll
        for (int i = 0; i < 8; i++) {
            int f  = tid + i * 256;
            int r  = f >> 5;
            int d4 = f & 31;
            *(float4*)&Vs[r * 128 + 4 * d4] =
                *(const float4*)(Vg + (size_t)(jt * 64 + r) * D_ + 4 * d4);
        }
        __syncthreads();

        float s[4][4];
#pragma unroll
        for (int i = 0; i < 4; i++)
#pragma unroll
            for (int j = 0; j < 4; j++) s[i][j] = 0.0f;

#pragma unroll 8
        for (int d = 0; d < 128; d++) {
            float qa[4], ka[4];
            *(float4*)qa = *(float4*)&Qt[d * 64 + 4 * ty];
            *(float4*)ka = *(float4*)&Kt[d * 64 + 4 * tx];
#pragma unroll
            for (int i = 0; i < 4; i++)
#pragma unroll
                for (int j = 0; j < 4; j++)
                    s[i][j] = fmaf(qa[i], ka[j], s[i][j]);
        }

        const float inv = 1.0f / 128.0f;
        const bool diag = (jt == qblk);
#pragma unroll
        for (int i = 0; i < 4; i++) {
            int ql = 4 * ty + i;
#pragma unroll
            for (int j = 0; j < 4; j++) {
                float val = s[i][j] * inv;
                if (diag && (ql < 4 * tx + j)) val = -1e30f;
                s[i][j] = val;
            }
        }

#pragma unroll
        for (int i = 0; i < 4; i++) {
            float tm = fmaxf(fmaxf(s[i][0], s[i][1]), fmaxf(s[i][2], s[i][3]));
#pragma unroll
            for (int off = 8; off > 0; off >>= 1)
                tm = fmaxf(tm, __shfl_xor_sync(0xffffffffu, tm, off, 16));
            float mn = fmaxf(m[i], tm);
            float al = __expf(m[i] - mn);
            m[i] = mn;
            float rs = 0.0f;
#pragma unroll
            for (int j = 0; j < 4; j++) {
                float p = __expf(s[i][j] - mn);
                s[i][j] = p;
                rs += p;
            }
#pragma unroll
            for (int off = 8; off > 0; off >>= 1)
                rs += __shfl_xor_sync(0xffffffffu, rs, off, 16);
            l[i] = l[i] * al + rs;
#pragma unroll
            for (int e = 0; e < 8; e++) acc[i][e] *= al;
            *(float4*)&Ps[(4 * ty + i) * 68 + 4 * tx] =
                make_float4(s[i][0], s[i][1], s[i][2], s[i][3]);
        }
        __syncthreads();

#pragma unroll 2
        for (int c = 0; c < 64; c++) {
            float pf[4];
#pragma unroll
            for (int i = 0; i < 4; i++) pf[i] = Ps[(4 * ty + i) * 68 + c];
            float vf[8];
            *(float4*)&vf[0] = *(float4*)&Vs[c * 128 + 8 * tx];
            *(float4*)&vf[4] = *(float4*)&Vs[c * 128 + 8 * tx + 4];
#pragma unroll
            for (int i = 0; i < 4; i++)
#pragma unroll
                for (int e = 0; e < 8; e++)
                    acc[i][e] = fmaf(pf[i], vf[e], acc[i][e]);
        }
    }

    const int b = bh >> 3, h = bh & 7;
#pragma unroll
    for (int i = 0; i < 4; i++) {
        float invl = 1.0f / l[i];
        int t = qblk * 64 + 4 * ty + i;
        float* dst = g_o + ((size_t)(b * T_ + t) * H_ + h) * D_ + 8 * tx;
        *(float4*)dst = make_float4(acc[i][0] * invl, acc[i][1] * invl,
                                    acc[i][2] * invl, acc[i][3] * invl);
        *(float4*)(dst + 4) = make_float4(acc[i][4] * invl, acc[i][5] * invl,
                                          acc[i][6] * invl, acc[i][7] * invl);
    }
}

// ---------------------------------------------------------------------------
extern "C" void kernel_launch(void* const* d_in, const int* in_sizes, int n_in,
                              void* d_out, int out_size)
{
    const float* x  = (const float*)d_in[0];
    const float* wq = (const float*)d_in[1];
    const float* wk = (const float*)d_in[2];
    const float* wv = (const float*)d_in[3];
    const float* wo = (const float*)d_in[4];
    float* out = (float*)d_out;

    cudaFuncSetAttribute(gemm_mma<0>,
                         cudaFuncAttributeMaxDynamicSharedMemorySize, GEMM_SMEM_BYTES);
    cudaFuncSetAttribute(gemm_mma<1>,
                         cudaFuncAttributeMaxDynamicSharedMemorySize, GEMM_SMEM_BYTES);

    // QKV projection (mma.sync tf32)
    gemm_mma<0><<<dim3(8, 32, 3), 256, GEMM_SMEM_BYTES>>>(x, wq, wk, wv, nullptr);

    // Fractional RoPE on q, k
    rope_kernel<<<dim3(T_, BH_), 64>>>();

    // Flash attention
    const int smem_bytes = (128 * 64 * 2 + 64 * 128 + 64 * 68) * (int)sizeof(float);
    cudaFuncSetAttribute(attn_kernel,
                         cudaFuncAttributeMaxDynamicSharedMemorySize, smem_bytes);
    attn_kernel<<<dim3(T_ / 64, BH_), 256, smem_bytes>>>();

    // Output projection (mma.sync tf32)
    gemm_mma<1><<<dim3(8, 32), 256, GEMM_SMEM_BYTES>>>(nullptr, wo, nullptr, nullptr, out);
}

// round 5
// speedup vs baseline: 2.7373x; 1.8424x over previous
#include <cuda_runtime.h>
#include <cstdint>
#include <math.h>

#define B_ 2
#define T_ 2048
#define M_ 1024
#define H_ 8
#define D_ 128
#define BH_ (B_*H_)

// Scratch (allocation-free: device globals)
__device__ float g_q[BH_ * T_ * D_];          // [B,H,T,D]
__device__ float g_k[BH_ * T_ * D_];          // [B,H,T,D]
__device__ float g_v[BH_ * T_ * D_];          // [B,H,T,D]
__device__ float g_o[B_ * T_ * H_ * D_];      // [B,T,H*D]

__device__ __forceinline__ uint32_t f2tf(float x) {
    uint32_t r;
    asm("cvt.rna.tf32.f32 %0, %1;" : "=r"(r) : "f"(x));
    return r;
}
__device__ __forceinline__ float ex2(float x) {
    float r;
    asm("ex2.approx.ftz.f32 %0, %1;" : "=f"(r) : "f"(x));
    return r;
}
__device__ __forceinline__ void mma_tf32(float c[4], const uint32_t a[4],
                                         const uint32_t b[2]) {
    asm volatile(
        "mma.sync.aligned.m16n8k8.row.col.f32.tf32.tf32.f32 "
        "{%0,%1,%2,%3}, {%4,%5,%6,%7}, {%8,%9}, {%0,%1,%2,%3};"
        : "+f"(c[0]), "+f"(c[1]), "+f"(c[2]), "+f"(c[3])
        : "r"(a[0]), "r"(a[1]), "r"(a[2]), "r"(a[3]), "r"(b[0]), "r"(b[1]));
}

// ---------------------------------------------------------------------------
// tf32 mma.sync GEMM (unchanged from R4): C[4096,1024] = A * W, W is [k][n].
// ---------------------------------------------------------------------------
#define AP 36
#define BP 136
#define AS_WORDS (128 * AP)
#define BS_WORDS (32 * BP)
#define GEMM_SMEM_BYTES ((2 * AS_WORDS + 2 * BS_WORDS) * 4)

template <int MODE>
__global__ void __launch_bounds__(256) gemm_mma(
    const float* __restrict__ Ain,
    const float* __restrict__ W0,
    const float* __restrict__ W1,
    const float* __restrict__ W2,
    float* __restrict__ Cout)
{
    extern __shared__ uint32_t smw[];
    uint32_t* As[2] = { smw, smw + AS_WORDS };
    uint32_t* Bs[2] = { smw + 2 * AS_WORDS, smw + 2 * AS_WORDS + BS_WORDS };

    const float* Ap;
    const float* W;
    float* O;
    if (MODE == 0) {
        Ap = Ain;
        W = (blockIdx.z == 0) ? W0 : (blockIdx.z == 1) ? W1 : W2;
        O = (blockIdx.z == 0) ? g_q : (blockIdx.z == 1) ? g_k : g_v;
    } else {
        Ap = g_o;
        W = W0;
        O = Cout;
    }

    const int tid  = threadIdx.x;
    const int lane = tid & 31;
    const int wid  = tid >> 5;
    const int wm   = wid & 1;
    const int wn   = wid >> 1;
    const int g    = lane >> 2;
    const int lq   = lane & 3;

    const int r0 = blockIdx.y * 128;
    const int c0 = blockIdx.x * 128;

    float acc[4][4][4];
#pragma unroll
    for (int i = 0; i < 4; i++)
#pragma unroll
        for (int j = 0; j < 4; j++)
#pragma unroll
            for (int e = 0; e < 4; e++) acc[i][j][e] = 0.0f;

    float4 ra[4], rb[4];

    auto stage = [&](int buf) {
#pragma unroll
        for (int it = 0; it < 4; it++) {
            int idx = tid + it * 256;
            int r = idx >> 3, k4 = idx & 7;
            uint4 va = make_uint4(f2tf(ra[it].x), f2tf(ra[it].y),
                                  f2tf(ra[it].z), f2tf(ra[it].w));
            *(uint4*)&As[buf][r * AP + 4 * k4] = va;
            int k = idx >> 5, n4 = idx & 31;
            uint4 vb = make_uint4(f2tf(rb[it].x), f2tf(rb[it].y),
                                  f2tf(rb[it].z), f2tf(rb[it].w));
            *(uint4*)&Bs[buf][k * BP + 4 * n4] = vb;
        }
    };

#pragma unroll
    for (int it = 0; it < 4; it++) {
        int idx = tid + it * 256;
        int r = idx >> 3, k4 = idx & 7;
        ra[it] = *(const float4*)(Ap + (size_t)(r0 + r) * 1024 + 4 * k4);
        int k = idx >> 5, n4 = idx & 31;
        rb[it] = *(const float4*)(W + (size_t)k * 1024 + c0 + 4 * n4);
    }
    stage(0);
    __syncthreads();

    for (int c = 0; c < 32; c++) {
        const int buf = c & 1;

        if (c < 31) {
            const int kc = (c + 1) * 32;
#pragma unroll
            for (int it = 0; it < 4; it++) {
                int idx = tid + it * 256;
                int r = idx >> 3, k4 = idx & 7;
                ra[it] = *(const float4*)(Ap + (size_t)(r0 + r) * 1024 + kc + 4 * k4);
                int k = idx >> 5, n4 = idx & 31;
                rb[it] = *(const float4*)(W + (size_t)(kc + k) * 1024 + c0 + 4 * n4);
            }
        }

#pragma unroll
        for (int ks = 0; ks < 4; ks++) {
            const int kk = ks * 8;
            uint32_t afr[4][4];
#pragma unroll
            for (int mf = 0; mf < 4; mf++) {
                const uint32_t* p = &As[buf][(wm * 64 + mf * 16 + g) * AP + kk + lq];
                afr[mf][0] = p[0];
                afr[mf][1] = p[8 * AP];
                afr[mf][2] = p[4];
                afr[mf][3] = p[8 * AP + 4];
            }
            uint32_t bfr[4][2];
#pragma unroll
            for (int nf = 0; nf < 4; nf++) {
                const uint32_t* p = &Bs[buf][(kk + lq) * BP + wn * 32 + nf * 8 + g];
                bfr[nf][0] = p[0];
                bfr[nf][1] = p[4 * BP];
            }
#pragma unroll
            for (int mf = 0; mf < 4; mf++)
#pragma unroll
                for (int nf = 0; nf < 4; nf++)
                    mma_tf32(acc[mf][nf], afr[mf], bfr[nf]);
        }
        __syncthreads();

        if (c < 31) {
            stage(buf ^ 1);
            __syncthreads();
        }
    }

#pragma unroll
    for (int mf = 0; mf < 4; mf++) {
#pragma unroll
        for (int half = 0; half < 2; half++) {
            int row = r0 + wm * 64 + mf * 16 + g + half * 8;
            float* dst;
            if (MODE == 0) {
                int bb = row >> 11, t = row & 2047;
                dst = O + ((size_t)(bb * H_ + blockIdx.x) * T_ + t) * D_;
            } else {
                dst = O + (size_t)row * 1024 + c0;
            }
#pragma unroll
            for (int nf = 0; nf < 4; nf++) {
                int col = wn * 32 + nf * 8 + 2 * lq;
                float2 v = half ? make_float2(acc[mf][nf][2], acc[mf][nf][3])
                                : make_float2(acc[mf][nf][0], acc[mf][nf][1]);
                *(float2*)(dst + col) = v;
            }
        }
    }
}

// ---------------------------------------------------------------------------
// Fractional RoPE, in-place on g_q/g_k.
// ---------------------------------------------------------------------------
__global__ void rope_kernel()
{
    const int t  = blockIdx.x;
    const int bh = blockIdx.y;
    const int d  = threadIdx.x & 31;
    float* base = ((threadIdx.x < 32) ? g_q : g_k) + ((size_t)bh * T_ + t) * D_;

    float freq = powf(10000.0f, -(float)d * (1.0f / 32.0f));
    float rad  = (float)t * freq;
    float sn, cs;
    sincosf(rad, &sn, &cs);
    float e = base[d], o = base[d + 32];
    base[d]      = e * cs - o * sn;
    base[d + 32] = e * sn + o * cs;
}

// ---------------------------------------------------------------------------
// Tensor-core flash attention (causal, scale 1/128), tf32 mma.sync.
// Br=64, Bc=64, 4 warps (128 thr); warp owns 16 q-rows; Q reg-resident.
// smem: KQ = max(Kt[128][72], Qstage[64][132]); Vs[64][136]; Ps[64][72]
// exp2-domain online softmax (MUFU.EX2). grid (T/64, BH).
// ---------------------------------------------------------------------------
#define KTP 72
#define QSP 132
#define VSP 136
#define PSP 72
#define KQ_WORDS (128 * KTP)                    // 9216 (>= 64*132=8448)
#define ATTN_SMEM_BYTES ((KQ_WORDS + 64 * VSP + 64 * PSP) * 4)  // 90112

__global__ void __launch_bounds__(128) attn_mma()
{
    extern __shared__ uint32_t smu[];
    uint32_t* KQ = smu;                      // Kt[d][r] pitch 72 / Qstage pitch 132
    uint32_t* Vs = smu + KQ_WORDS;           // [64][136]
    uint32_t* Ps = Vs + 64 * VSP;            // [64][72]

    const int qblk = blockIdx.x;             // 0..31
    const int bh   = blockIdx.y;
    const float* Qg = g_q + (size_t)bh * T_ * D_ + (size_t)qblk * 64 * D_;
    const float* Kg = g_k + (size_t)bh * T_ * D_;
    const float* Vg = g_v + (size_t)bh * T_ * D_;

    const int tid  = threadIdx.x;
    const int lane = tid & 31;
    const int wr   = tid >> 5;               // warp row block 0..3
    const int g    = lane >> 2;
    const int lq   = lane & 3;

    // ---- stage Q (64x128) to smem tf32, pitch 132 ----
#pragma unroll
    for (int it = 0; it < 16; it++) {
        int idx = tid + it * 128;
        int r = idx >> 5, d4 = idx & 31;
        float4 v = *(const float4*)(Qg + (size_t)r * D_ + 4 * d4);
        uint4 u = make_uint4(f2tf(v.x), f2tf(v.y), f2tf(v.z), f2tf(v.w));
        *(uint4*)&KQ[r * QSP + 4 * d4] = u;
    }
    __syncthreads();

    // ---- Q A-fragments, register resident: 16 k-steps x 4 regs ----
    uint32_t qfr[16][4];
#pragma unroll
    for (int ks = 0; ks < 16; ks++) {
        const uint32_t* p = &KQ[(wr * 16 + g) * QSP + 8 * ks + lq];
        qfr[ks][0] = p[0];
        qfr[ks][1] = p[8 * QSP];
        qfr[ks][2] = p[4];
        qfr[ks][3] = p[8 * QSP + 4];
    }

    float oacc[16][4];
#pragma unroll
    for (int nf = 0; nf < 16; nf++)
#pragma unroll
        for (int e = 0; e < 4; e++) oacc[nf][e] = 0.0f;
    float mrow[2] = { -1e30f, -1e30f };
    float lrow[2] = { 0.0f, 0.0f };

    const float Kc = 1.44269504f / 128.0f;    // log2(e)/HEAD_DIM

    for (int jt = 0; jt <= qblk; jt++) {
        __syncthreads();   // all warps done consuming previous K/V

        // K tile: 64 rows x 128 d -> Kt[d][r] (tf32, pitch 72)
#pragma unroll
        for (int it = 0; it < 16; it++) {
            int idx = tid + it * 128;
            int d4 = idx >> 6, r = idx & 63;
            float4 v = *(const float4*)(Kg + (size_t)(jt * 64 + r) * D_ + 4 * d4);
            KQ[(4 * d4 + 0) * KTP + r] = f2tf(v.x);
            KQ[(4 * d4 + 1) * KTP + r] = f2tf(v.y);
            KQ[(4 * d4 + 2) * KTP + r] = f2tf(v.z);
            KQ[(4 * d4 + 3) * KTP + r] = f2tf(v.w);
        }
        // V tile: 64 x 128 row-major (tf32, pitch 136)
#pragma unroll
        for (int it = 0; it < 16; it++) {
            int idx = tid + it * 128;
            int r = idx >> 5, d4 = idx & 31;
            float4 v = *(const float4*)(Vg + (size_t)(jt * 64 + r) * D_ + 4 * d4);
            uint4 u = make_uint4(f2tf(v.x), f2tf(v.y), f2tf(v.z), f2tf(v.w));
            *(uint4*)&Vs[r * VSP + 4 * d4] = u;
        }
        __syncthreads();

        // ---- S = Q K^T : 16 k-steps x 8 n-frags ----
        float sacc[8][4];
#pragma unroll
        for (int nf = 0; nf < 8; nf++)
#pragma unroll
            for (int e = 0; e < 4; e++) sacc[nf][e] = 0.0f;

#pragma unroll
        for (int ks = 0; ks < 16; ks++) {
            uint32_t bfr[8][2];
#pragma unroll
            for (int nf = 0; nf < 8; nf++) {
                const uint32_t* p = &KQ[(8 * ks + lq) * KTP + 8 * nf + g];
                bfr[nf][0] = p[0];
                bfr[nf][1] = p[4 * KTP];
            }
#pragma unroll
            for (int nf = 0; nf < 8; nf++)
                mma_tf32(sacc[nf], qfr[ks], bfr[nf]);
        }

        // ---- softmax (exp2 domain), per-thread 2 rows x 16 cols ----
#pragma unroll
        for (int nf = 0; nf < 8; nf++)
#pragma unroll
            for (int e = 0; e < 4; e++) sacc[nf][e] *= Kc;

        if (jt == qblk) {
#pragma unroll
            for (int nf = 0; nf < 8; nf++)
#pragma unroll
                for (int e = 0; e < 4; e++) {
                    int col = nf * 8 + 2 * lq + (e & 1);
                    int row = wr * 16 + g + (e >> 1) * 8;
                    if (col > row) sacc[nf][e] = -1e30f;
                }
        }

        float zmax[2] = { -1e30f, -1e30f };
#pragma unroll
        for (int nf = 0; nf < 8; nf++) {
            zmax[0] = fmaxf(zmax[0], fmaxf(sacc[nf][0], sacc[nf][1]));
            zmax[1] = fmaxf(zmax[1], fmaxf(sacc[nf][2], sacc[nf][3]));
        }
#pragma unroll
        for (int off = 1; off <= 2; off <<= 1) {
            zmax[0] = fmaxf(zmax[0], __shfl_xor_sync(0xffffffffu, zmax[0], off));
            zmax[1] = fmaxf(zmax[1], __shfl_xor_sync(0xffffffffu, zmax[1], off));
        }

        float alpha[2], psum[2] = { 0.0f, 0.0f };
#pragma unroll
        for (int rr = 0; rr < 2; rr++) {
            float mn = fmaxf(mrow[rr], zmax[rr]);
            alpha[rr] = ex2(mrow[rr] - mn);
            mrow[rr] = mn;
        }
#pragma unroll
        for (int nf = 0; nf < 8; nf++) {
            float p0 = ex2(sacc[nf][0] - mrow[0]);
            float p1 = ex2(sacc[nf][1] - mrow[0]);
            float p2 = ex2(sacc[nf][2] - mrow[1]);
            float p3 = ex2(sacc[nf][3] - mrow[1]);
            sacc[nf][0] = p0; sacc[nf][1] = p1;
            sacc[nf][2] = p2; sacc[nf][3] = p3;
            psum[0] += p0 + p1;
            psum[1] += p2 + p3;
        }
#pragma unroll
        for (int off = 1; off <= 2; off <<= 1) {
            psum[0] += __shfl_xor_sync(0xffffffffu, psum[0], off);
            psum[1] += __shfl_xor_sync(0xffffffffu, psum[1], off);
        }
        lrow[0] = lrow[0] * alpha[0] + psum[0];
        lrow[1] = lrow[1] * alpha[1] + psum[1];
#pragma unroll
        for (int nf = 0; nf < 16; nf++) {
            oacc[nf][0] *= alpha[0]; oacc[nf][1] *= alpha[0];
            oacc[nf][2] *= alpha[1]; oacc[nf][3] *= alpha[1];
        }

        // ---- P -> smem (tf32), C-layout to A-layout via warp-private region ----
#pragma unroll
        for (int nf = 0; nf < 8; nf++) {
            uint2 u0 = make_uint2(f2tf(sacc[nf][0]), f2tf(sacc[nf][1]));
            uint2 u1 = make_uint2(f2tf(sacc[nf][2]), f2tf(sacc[nf][3]));
            *(uint2*)&Ps[(wr * 16 + g) * PSP + 8 * nf + 2 * lq] = u0;
            *(uint2*)&Ps[(wr * 16 + g + 8) * PSP + 8 * nf + 2 * lq] = u1;
        }
        __syncwarp();

        // ---- O += P V : 8 k-steps x 16 n-frags ----
#pragma unroll
        for (int ks = 0; ks < 8; ks++) {
            uint32_t pfr[4];
            const uint32_t* pp = &Ps[(wr * 16 + g) * PSP + 8 * ks + lq];
            pfr[0] = pp[0];
            pfr[1] = pp[8 * PSP];
            pfr[2] = pp[4];
            pfr[3] = pp[8 * PSP + 4];
#pragma unroll
            for (int nf = 0; nf < 16; nf++) {
                uint32_t vfr[2];
                const uint32_t* vp = &Vs[(8 * ks + lq) * VSP + 8 * nf + g];
                vfr[0] = vp[0];
                vfr[1] = vp[4 * VSP];
                mma_tf32(oacc[nf], pfr, vfr);
            }
        }
    }

    // ---- epilogue: normalize, write g_o [B,T,H*D] ----
    const int b = bh >> 3, h = bh & 7;
    const float invl0 = 1.0f / lrow[0];
    const float invl1 = 1.0f / lrow[1];
    const int t0 = qblk * 64 + wr * 16 + g;
    float* dst0 = g_o + ((size_t)(b * T_ + t0) * H_ + h) * D_;
    float* dst1 = g_o + ((size_t)(b * T_ + t0 + 8) * H_ + h) * D_;
#pragma unroll
    for (int nf = 0; nf < 16; nf++) {
        int col = 8 * nf + 2 * lq;
        *(float2*)(dst0 + col) = make_float2(oacc[nf][0] * invl0, oacc[nf][1] * invl0);
        *(float2*)(dst1 + col) = make_float2(oacc[nf][2] * invl1, oacc[nf][3] * invl1);
    }
}

// ---------------------------------------------------------------------------
extern "C" void kernel_launch(void* const* d_in, const int* in_sizes, int n_in,
                              void* d_out, int out_size)
{
    const float* x  = (const float*)d_in[0];
    const float* wq = (const float*)d_in[1];
    const float* wk = (const float*)d_in[2];
    const float* wv = (const float*)d_in[3];
    const float* wo = (const float*)d_in[4];
    float* out = (float*)d_out;

    cudaFuncSetAttribute(gemm_mma<0>,
                         cudaFuncAttributeMaxDynamicSharedMemorySize, GEMM_SMEM_BYTES);
    cudaFuncSetAttribute(gemm_mma<1>,
                         cudaFuncAttributeMaxDynamicSharedMemorySize, GEMM_SMEM_BYTES);
    cudaFuncSetAttribute(attn_mma,
                         cudaFuncAttributeMaxDynamicSharedMemorySize, ATTN_SMEM_BYTES);

    // QKV projection (mma.sync tf32)
    gemm_mma<0><<<dim3(8, 32, 3), 256, GEMM_SMEM_BYTES>>>(x, wq, wk, wv, nullptr);

    // Fractional RoPE on q, k
    rope_kernel<<<dim3(T_, BH_), 64>>>();

    // Tensor-core flash attention
    attn_mma<<<dim3(T_ / 64, BH_), 128, ATTN_SMEM_BYTES>>>();

    // Output projection (mma.sync tf32)
    gemm_mma<1><<<dim3(8, 32), 256, GEMM_SMEM_BYTES>>>(nullptr, wo, nullptr, nullptr, out);
}

// round 6
// speedup vs baseline: 3.2857x; 1.2003x over previous
#include <cuda_runtime.h>
#include <cstdint>
#include <math.h>

#define B_ 2
#define T_ 2048
#define M_ 1024
#define H_ 8
#define D_ 128
#define BH_ (B_*H_)

// Scratch (allocation-free: device globals)
__device__ float    g_q[BH_ * T_ * D_];        // [B,H,T,D] f32
__device__ float    g_k[BH_ * T_ * D_];        // [B,H,T,D] f32
__device__ float    g_v[BH_ * T_ * D_];        // [B,H,T,D] f32
__device__ uint32_t g_ot[B_ * T_ * H_ * D_];   // [B,T,H*D] tf32 (attention out)
__device__ uint32_t g_xt[B_ * T_ * M_];        // tf32(x)
__device__ uint32_t g_wtf[4 * M_ * M_];        // tf32(wq,wk,wv,wo)

__device__ __forceinline__ uint32_t f2tf(float x) {
    uint32_t r;
    asm("cvt.rna.tf32.f32 %0, %1;" : "=r"(r) : "f"(x));
    return r;
}
__device__ __forceinline__ float ex2(float x) {
    float r;
    asm("ex2.approx.ftz.f32 %0, %1;" : "=f"(r) : "f"(x));
    return r;
}
__device__ __forceinline__ void mma_tf32(float c[4], const uint32_t a[4],
                                         const uint32_t b[2]) {
    asm volatile(
        "mma.sync.aligned.m16n8k8.row.col.f32.tf32.tf32.f32 "
        "{%0,%1,%2,%3}, {%4,%5,%6,%7}, {%8,%9}, {%0,%1,%2,%3};"
        : "+f"(c[0]), "+f"(c[1]), "+f"(c[2]), "+f"(c[3])
        : "r"(a[0]), "r"(a[1]), "r"(a[2]), "r"(a[3]), "r"(b[0]), "r"(b[1]));
}
__device__ __forceinline__ void cp16(uint32_t smem_dst, const void* gptr) {
    asm volatile("cp.async.cg.shared.global [%0], [%1], 16;"
                 :: "r"(smem_dst), "l"(gptr));
}
#define CP_COMMIT() asm volatile("cp.async.commit_group;" ::: "memory")
#define CP_WAIT(n)  asm volatile("cp.async.wait_group %0;" :: "n"(n) : "memory")

// ---------------------------------------------------------------------------
// tf32 pre-conversion
// ---------------------------------------------------------------------------
__global__ void conv_x(const float* __restrict__ x)
{
    int i = blockIdx.x * 256 + threadIdx.x;           // f4 index; grid 4096
    float4 v = ((const float4*)x)[i];
    ((uint4*)g_xt)[i] = make_uint4(f2tf(v.x), f2tf(v.y), f2tf(v.z), f2tf(v.w));
}
__global__ void conv_w(const float* __restrict__ wq, const float* __restrict__ wk,
                       const float* __restrict__ wv, const float* __restrict__ wo)
{
    const float* src = (blockIdx.y == 0) ? wq : (blockIdx.y == 1) ? wk
                     : (blockIdx.y == 2) ? wv : wo;
    uint4* dst = (uint4*)(g_wtf + (size_t)blockIdx.y * M_ * M_);
    int i = blockIdx.x * 256 + threadIdx.x;           // f4 index; grid 1024
    float4 v = ((const float4*)src)[i];
    dst[i] = make_uint4(f2tf(v.x), f2tf(v.y), f2tf(v.z), f2tf(v.w));
}

// ---------------------------------------------------------------------------
// tf32 mma.sync GEMM with 3-stage cp.async pipeline.
// C[4096,1024] = A * W (both pre-converted tf32; W is [k][n]).
// 128x128 CTA tile, 8 warps (2m x 4n), warp tile 64x32, K-chunk 32.
// MODE 0: A = g_xt, W = g_wtf[z], scatter f32 into g_q/g_k/g_v [B,H,T,D].
// MODE 1: A = g_ot, W = g_wtf[3], f32 row-major store to Cout.
// ---------------------------------------------------------------------------
#define AP 36
#define BP 136
#define AS_WORDS (128 * AP)                    // 4608
#define BS_WORDS (32 * BP)                     // 4352
#define STG_WORDS (AS_WORDS + BS_WORDS)        // 8960
#define GEMM_SMEM_BYTES (3 * STG_WORDS * 4)    // 107520

template <int MODE>
__global__ void __launch_bounds__(256, 2) gemm_cp(float* __restrict__ Cout)
{
    extern __shared__ uint32_t smw[];

    const uint32_t* Ap;
    const uint32_t* W;
    float* O;
    if (MODE == 0) {
        Ap = g_xt;
        W  = g_wtf + (size_t)blockIdx.z * M_ * M_;
        O  = (blockIdx.z == 0) ? g_q : (blockIdx.z == 1) ? g_k : g_v;
    } else {
        Ap = g_ot;
        W  = g_wtf + (size_t)3 * M_ * M_;
        O  = Cout;
    }

    const int tid  = threadIdx.x;
    const int lane = tid & 31;
    const int wid  = tid >> 5;
    const int wm   = wid & 1;
    const int wn   = wid >> 1;
    const int g    = lane >> 2;
    const int lq   = lane & 3;

    const int r0 = blockIdx.y * 128;
    const int c0 = blockIdx.x * 128;

    const uint32_t smbase = (uint32_t)__cvta_generic_to_shared(smw);

    auto issue = [&](int c) {
        const int s = c % 3;
        const uint32_t aB = smbase + s * STG_WORDS * 4;
        const uint32_t bB = aB + AS_WORDS * 4;
        const int kc = c * 32;
#pragma unroll
        for (int it = 0; it < 4; it++) {
            int idx = tid + it * 256;
            int r = idx >> 3, k4 = idx & 7;
            cp16(aB + (r * AP + 4 * k4) * 4,
                 Ap + (size_t)(r0 + r) * 1024 + kc + 4 * k4);
            int k = idx >> 5, n4 = idx & 31;
            cp16(bB + (k * BP + 4 * n4) * 4,
                 W + (size_t)(kc + k) * 1024 + c0 + 4 * n4);
        }
        CP_COMMIT();
    };

    float acc[4][4][4];
#pragma unroll
    for (int i = 0; i < 4; i++)
#pragma unroll
        for (int j = 0; j < 4; j++)
#pragma unroll
            for (int e = 0; e < 4; e++) acc[i][j][e] = 0.0f;

    issue(0);
    issue(1);

    for (int c = 0; c < 32; c++) {
        if (c < 30) { CP_WAIT(1); } else { CP_WAIT(0); }
        __syncthreads();

        const uint32_t* As = smw + (c % 3) * STG_WORDS;
        const uint32_t* Bs = As + AS_WORDS;

#pragma unroll
        for (int ks = 0; ks < 4; ks++) {
            const int kk = ks * 8;
            uint32_t afr[4][4];
#pragma unroll
            for (int mf = 0; mf < 4; mf++) {
                const uint32_t* p = &As[(wm * 64 + mf * 16 + g) * AP + kk + lq];
                afr[mf][0] = p[0];
                afr[mf][1] = p[8 * AP];
                afr[mf][2] = p[4];
                afr[mf][3] = p[8 * AP + 4];
            }
            uint32_t bfr[4][2];
#pragma unroll
            for (int nf = 0; nf < 4; nf++) {
                const uint32_t* p = &Bs[(kk + lq) * BP + wn * 32 + nf * 8 + g];
                bfr[nf][0] = p[0];
                bfr[nf][1] = p[4 * BP];
            }
#pragma unroll
            for (int mf = 0; mf < 4; mf++)
#pragma unroll
                for (int nf = 0; nf < 4; nf++)
                    mma_tf32(acc[mf][nf], afr[mf], bfr[nf]);
        }

        if (c + 2 < 32) issue(c + 2);
    }

    // ---- epilogue (f32 stores) ----
#pragma unroll
    for (int mf = 0; mf < 4; mf++) {
#pragma unroll
        for (int half = 0; half < 2; half++) {
            int row = r0 + wm * 64 + mf * 16 + g + half * 8;
            float* dst;
            if (MODE == 0) {
                int bb = row >> 11, t = row & 2047;
                dst = O + ((size_t)(bb * H_ + blockIdx.x) * T_ + t) * D_;
            } else {
                dst = O + (size_t)row * 1024 + c0;
            }
#pragma unroll
            for (int nf = 0; nf < 4; nf++) {
                int col = wn * 32 + nf * 8 + 2 * lq;
                float2 v = half ? make_float2(acc[mf][nf][2], acc[mf][nf][3])
                                : make_float2(acc[mf][nf][0], acc[mf][nf][1]);
                *(float2*)(dst + col) = v;
            }
        }
    }
}

// ---------------------------------------------------------------------------
// Fractional RoPE, in-place on g_q/g_k.
// ---------------------------------------------------------------------------
__global__ void rope_kernel()
{
    const int t  = blockIdx.x;
    const int bh = blockIdx.y;
    const int d  = threadIdx.x & 31;
    float* base = ((threadIdx.x < 32) ? g_q : g_k) + ((size_t)bh * T_ + t) * D_;

    float freq = powf(10000.0f, -(float)d * (1.0f / 32.0f));
    float rad  = (float)t * freq;
    float sn, cs;
    sincosf(rad, &sn, &cs);
    float e = base[d], o = base[d + 32];
    base[d]      = e * cs - o * sn;
    base[d + 32] = e * sn + o * cs;
}

// ---------------------------------------------------------------------------
// Tensor-core flash attention (causal, scale 1/128), tf32 mma.sync.
// Br=64, Bc=64, 4 warps; Q reg-resident; exp2-domain online softmax.
// qblk processed in REVERSE launch order (longest CTAs first).
// Output written as tf32 into g_ot [B,T,H*D].
// ---------------------------------------------------------------------------
#define KTP 72
#define QSP 132
#define VSP 136
#define PSP 72
#define KQ_WORDS (128 * KTP)
#define ATTN_SMEM_BYTES ((KQ_WORDS + 64 * VSP + 64 * PSP) * 4)  // 90112

__global__ void __launch_bounds__(128) attn_mma()
{
    extern __shared__ uint32_t smu[];
    uint32_t* KQ = smu;
    uint32_t* Vs = smu + KQ_WORDS;
    uint32_t* Ps = Vs + 64 * VSP;

    const int qblk = gridDim.x - 1 - blockIdx.x;   // longest first
    const int bh   = blockIdx.y;
    const float* Qg = g_q + (size_t)bh * T_ * D_ + (size_t)qblk * 64 * D_;
    const float* Kg = g_k + (size_t)bh * T_ * D_;
    const float* Vg = g_v + (size_t)bh * T_ * D_;

    const int tid  = threadIdx.x;
    const int lane = tid & 31;
    const int wr   = tid >> 5;
    const int g    = lane >> 2;
    const int lq   = lane & 3;

#pragma unroll
    for (int it = 0; it < 16; it++) {
        int idx = tid + it * 128;
        int r = idx >> 5, d4 = idx & 31;
        float4 v = *(const float4*)(Qg + (size_t)r * D_ + 4 * d4);
        uint4 u = make_uint4(f2tf(v.x), f2tf(v.y), f2tf(v.z), f2tf(v.w));
        *(uint4*)&KQ[r * QSP + 4 * d4] = u;
    }
    __syncthreads();

    uint32_t qfr[16][4];
#pragma unroll
    for (int ks = 0; ks < 16; ks++) {
        const uint32_t* p = &KQ[(wr * 16 + g) * QSP + 8 * ks + lq];
        qfr[ks][0] = p[0];
        qfr[ks][1] = p[8 * QSP];
        qfr[ks][2] = p[4];
        qfr[ks][3] = p[8 * QSP + 4];
    }

    float oacc[16][4];
#pragma unroll
    for (int nf = 0; nf < 16; nf++)
#pragma unroll
        for (int e = 0; e < 4; e++) oacc[nf][e] = 0.0f;
    float mrow[2] = { -1e30f, -1e30f };
    float lrow[2] = { 0.0f, 0.0f };

    const float Kc = 1.44269504f / 128.0f;

    for (int jt = 0; jt <= qblk; jt++) {
        __syncthreads();

#pragma unroll
        for (int it = 0; it < 16; it++) {
            int idx = tid + it * 128;
            int d4 = idx >> 6, r = idx & 63;
            float4 v = *(const float4*)(Kg + (size_t)(jt * 64 + r) * D_ + 4 * d4);
            KQ[(4 * d4 + 0) * KTP + r] = f2tf(v.x);
            KQ[(4 * d4 + 1) * KTP + r] = f2tf(v.y);
            KQ[(4 * d4 + 2) * KTP + r] = f2tf(v.z);
            KQ[(4 * d4 + 3) * KTP + r] = f2tf(v.w);
        }
#pragma unroll
        for (int it = 0; it < 16; it++) {
            int idx = tid + it * 128;
            int r = idx >> 5, d4 = idx & 31;
            float4 v = *(const float4*)(Vg + (size_t)(jt * 64 + r) * D_ + 4 * d4);
            uint4 u = make_uint4(f2tf(v.x), f2tf(v.y), f2tf(v.z), f2tf(v.w));
            *(uint4*)&Vs[r * VSP + 4 * d4] = u;
        }
        __syncthreads();

        float sacc[8][4];
#pragma unroll
        for (int nf = 0; nf < 8; nf++)
#pragma unroll
            for (int e = 0; e < 4; e++) sacc[nf][e] = 0.0f;

#pragma unroll
        for (int ks = 0; ks < 16; ks++) {
            uint32_t bfr[8][2];
#pragma unroll
            for (int nf = 0; nf < 8; nf++) {
                const uint32_t* p = &KQ[(8 * ks + lq) * KTP + 8 * nf + g];
                bfr[nf][0] = p[0];
                bfr[nf][1] = p[4 * KTP];
            }
#pragma unroll
            for (int nf = 0; nf < 8; nf++)
                mma_tf32(sacc[nf], qfr[ks], bfr[nf]);
        }

#pragma unroll
        for (int nf = 0; nf < 8; nf++)
#pragma unroll
            for (int e = 0; e < 4; e++) sacc[nf][e] *= Kc;

        if (jt == qblk) {
#pragma unroll
            for (int nf = 0; nf < 8; nf++)
#pragma unroll
                for (int e = 0; e < 4; e++) {
                    int col = nf * 8 + 2 * lq + (e & 1);
                    int row = wr * 16 + g + (e >> 1) * 8;
                    if (col > row) sacc[nf][e] = -1e30f;
                }
        }

        float zmax[2] = { -1e30f, -1e30f };
#pragma unroll
        for (int nf = 0; nf < 8; nf++) {
            zmax[0] = fmaxf(zmax[0], fmaxf(sacc[nf][0], sacc[nf][1]));
            zmax[1] = fmaxf(zmax[1], fmaxf(sacc[nf][2], sacc[nf][3]));
        }
#pragma unroll
        for (int off = 1; off <= 2; off <<= 1) {
            zmax[0] = fmaxf(zmax[0], __shfl_xor_sync(0xffffffffu, zmax[0], off));
            zmax[1] = fmaxf(zmax[1], __shfl_xor_sync(0xffffffffu, zmax[1], off));
        }

        float alpha[2], psum[2] = { 0.0f, 0.0f };
#pragma unroll
        for (int rr = 0; rr < 2; rr++) {
            float mn = fmaxf(mrow[rr], zmax[rr]);
            alpha[rr] = ex2(mrow[rr] - mn);
            mrow[rr] = mn;
        }
#pragma unroll
        for (int nf = 0; nf < 8; nf++) {
            float p0 = ex2(sacc[nf][0] - mrow[0]);
            float p1 = ex2(sacc[nf][1] - mrow[0]);
            float p2 = ex2(sacc[nf][2] - mrow[1]);
            float p3 = ex2(sacc[nf][3] - mrow[1]);
            sacc[nf][0] = p0; sacc[nf][1] = p1;
            sacc[nf][2] = p2; sacc[nf][3] = p3;
            psum[0] += p0 + p1;
            psum[1] += p2 + p3;
        }
#pragma unroll
        for (int off = 1; off <= 2; off <<= 1) {
            psum[0] += __shfl_xor_sync(0xffffffffu, psum[0], off);
            psum[1] += __shfl_xor_sync(0xffffffffu, psum[1], off);
        }
        lrow[0] = lrow[0] * alpha[0] + psum[0];
        lrow[1] = lrow[1] * alpha[1] + psum[1];
#pragma unroll
        for (int nf = 0; nf < 16; nf++) {
            oacc[nf][0] *= alpha[0]; oacc[nf][1] *= alpha[0];
            oacc[nf][2] *= alpha[1]; oacc[nf][3] *= alpha[1];
        }

#pragma unroll
        for (int nf = 0; nf < 8; nf++) {
            uint2 u0 = make_uint2(f2tf(sacc[nf][0]), f2tf(sacc[nf][1]));
            uint2 u1 = make_uint2(f2tf(sacc[nf][2]), f2tf(sacc[nf][3]));
            *(uint2*)&Ps[(wr * 16 + g) * PSP + 8 * nf + 2 * lq] = u0;
            *(uint2*)&Ps[(wr * 16 + g + 8) * PSP + 8 * nf + 2 * lq] = u1;
        }
        __syncwarp();

#pragma unroll
        for (int ks = 0; ks < 8; ks++) {
            uint32_t pfr[4];
            const uint32_t* pp = &Ps[(wr * 16 + g) * PSP + 8 * ks + lq];
            pfr[0] = pp[0];
            pfr[1] = pp[8 * PSP];
            pfr[2] = pp[4];
            pfr[3] = pp[8 * PSP + 4];
#pragma unroll
            for (int nf = 0; nf < 16; nf++) {
                uint32_t vfr[2];
                const uint32_t* vp = &Vs[(8 * ks + lq) * VSP + 8 * nf + g];
                vfr[0] = vp[0];
                vfr[1] = vp[4 * VSP];
                mma_tf32(oacc[nf], pfr, vfr);
            }
        }
    }

    // ---- epilogue: normalize, write tf32 into g_ot [B,T,H*D] ----
    const int b = bh >> 3, h = bh & 7;
    const float invl0 = 1.0f / lrow[0];
    const float invl1 = 1.0f / lrow[1];
    const int t0 = qblk * 64 + wr * 16 + g;
    uint32_t* dst0 = g_ot + ((size_t)(b * T_ + t0) * H_ + h) * D_;
    uint32_t* dst1 = g_ot + ((size_t)(b * T_ + t0 + 8) * H_ + h) * D_;
#pragma unroll
    for (int nf = 0; nf < 16; nf++) {
        int col = 8 * nf + 2 * lq;
        *(uint2*)(dst0 + col) = make_uint2(f2tf(oacc[nf][0] * invl0),
                                           f2tf(oacc[nf][1] * invl0));
        *(uint2*)(dst1 + col) = make_uint2(f2tf(oacc[nf][2] * invl1),
                                           f2tf(oacc[nf][3] * invl1));
    }
}

// ---------------------------------------------------------------------------
extern "C" void kernel_launch(void* const* d_in, const int* in_sizes, int n_in,
                              void* d_out, int out_size)
{
    const float* x  = (const float*)d_in[0];
    const float* wq = (const float*)d_in[1];
    const float* wk = (const float*)d_in[2];
    const float* wv = (const float*)d_in[3];
    const float* wo = (const float*)d_in[4];
    float* out = (float*)d_out;

    cudaFuncSetAttribute(gemm_cp<0>,
                         cudaFuncAttributeMaxDynamicSharedMemorySize, GEMM_SMEM_BYTES);
    cudaFuncSetAttribute(gemm_cp<1>,
                         cudaFuncAttributeMaxDynamicSharedMemorySize, GEMM_SMEM_BYTES);
    cudaFuncSetAttribute(attn_mma,
                         cudaFuncAttributeMaxDynamicSharedMemorySize, ATTN_SMEM_BYTES);

    // tf32 pre-conversion of x and weights
    conv_x<<<4096, 256>>>(x);
    conv_w<<<dim3(1024, 4), 256>>>(wq, wk, wv, wo);

    // QKV projection (cp.async + mma.sync tf32)
    gemm_cp<0><<<dim3(8, 32, 3), 256, GEMM_SMEM_BYTES>>>(nullptr);

    // Fractional RoPE on q, k
    rope_kernel<<<dim3(T_, BH_), 64>>>();

    // Tensor-core flash attention (writes tf32 g_ot)
    attn_mma<<<dim3(T_ / 64, BH_), 128, ATTN_SMEM_BYTES>>>();

    // Output projection
    gemm_cp<1><<<dim3(8, 32), 256, GEMM_SMEM_BYTES>>>(out);
}

// round 7
// speedup vs baseline: 4.0565x; 1.2346x over previous
#include <cuda_runtime.h>
#include <cstdint>
#include <math.h>

#define B_ 2
#define T_ 2048
#define M_ 1024
#define H_ 8
#define D_ 128
#define BH_ (B_*H_)

// Scratch (allocation-free: device globals)
__device__ float    g_q[BH_ * T_ * D_];        // [B,H,T,D] f32 (pre-rope)
__device__ float    g_k[BH_ * T_ * D_];        // [B,H,T,D] f32 (pre-rope)
__device__ uint32_t g_qt[BH_ * T_ * D_];       // tf32 q (post-rope)
__device__ uint32_t g_kt[BH_ * T_ * D_];       // tf32 k (post-rope)
__device__ uint32_t g_vt[BH_ * T_ * D_];       // tf32 v
__device__ uint32_t g_ot[B_ * T_ * H_ * D_];   // [B,T,H*D] tf32 (attention out)
__device__ uint32_t g_xt[B_ * T_ * M_];        // tf32(x)
__device__ uint32_t g_wtf[4 * M_ * M_];        // tf32(wq,wk,wv,wo)

__device__ __forceinline__ uint32_t f2tf(float x) {
    uint32_t r;
    asm("cvt.rna.tf32.f32 %0, %1;" : "=r"(r) : "f"(x));
    return r;
}
__device__ __forceinline__ float ex2(float x) {
    float r;
    asm("ex2.approx.ftz.f32 %0, %1;" : "=f"(r) : "f"(x));
    return r;
}
__device__ __forceinline__ void mma_tf32(float c[4], const uint32_t a[4],
                                         const uint32_t b[2]) {
    asm volatile(
        "mma.sync.aligned.m16n8k8.row.col.f32.tf32.tf32.f32 "
        "{%0,%1,%2,%3}, {%4,%5,%6,%7}, {%8,%9}, {%0,%1,%2,%3};"
        : "+f"(c[0]), "+f"(c[1]), "+f"(c[2]), "+f"(c[3])
        : "r"(a[0]), "r"(a[1]), "r"(a[2]), "r"(a[3]), "r"(b[0]), "r"(b[1]));
}
__device__ __forceinline__ void cp16(uint32_t smem_dst, const void* gptr) {
    asm volatile("cp.async.cg.shared.global [%0], [%1], 16;"
                 :: "r"(smem_dst), "l"(gptr));
}
#define CP_COMMIT() asm volatile("cp.async.commit_group;" ::: "memory")
#define CP_WAIT(n)  asm volatile("cp.async.wait_group %0;" :: "n"(n) : "memory")

// ---------------------------------------------------------------------------
// tf32 pre-conversion
// ---------------------------------------------------------------------------
__global__ void conv_x(const float* __restrict__ x)
{
    int i = blockIdx.x * 256 + threadIdx.x;
    float4 v = ((const float4*)x)[i];
    ((uint4*)g_xt)[i] = make_uint4(f2tf(v.x), f2tf(v.y), f2tf(v.z), f2tf(v.w));
}
__global__ void conv_w(const float* __restrict__ wq, const float* __restrict__ wk,
                       const float* __restrict__ wv, const float* __restrict__ wo)
{
    const float* src = (blockIdx.y == 0) ? wq : (blockIdx.y == 1) ? wk
                     : (blockIdx.y == 2) ? wv : wo;
    uint4* dst = (uint4*)(g_wtf + (size_t)blockIdx.y * M_ * M_);
    int i = blockIdx.x * 256 + threadIdx.x;
    float4 v = ((const float4*)src)[i];
    dst[i] = make_uint4(f2tf(v.x), f2tf(v.y), f2tf(v.z), f2tf(v.w));
}

// ---------------------------------------------------------------------------
// tf32 mma.sync GEMM with 3-stage cp.async pipeline.
// MODE 0: A = g_xt, W = g_wtf[z]; z=0,1 -> f32 g_q/g_k; z=2 -> tf32 g_vt.
// MODE 1: A = g_ot, W = g_wtf[3], f32 row-major store to Cout.
// ---------------------------------------------------------------------------
#define AP 36
#define BP 136
#define AS_WORDS (128 * AP)
#define BS_WORDS (32 * BP)
#define STG_WORDS (AS_WORDS + BS_WORDS)
#define GEMM_SMEM_BYTES (3 * STG_WORDS * 4)    // 107520

template <int MODE>
__global__ void __launch_bounds__(256, 2) gemm_cp(float* __restrict__ Cout)
{
    extern __shared__ uint32_t smw[];

    const uint32_t* Ap;
    const uint32_t* W;
    if (MODE == 0) {
        Ap = g_xt;
        W  = g_wtf + (size_t)blockIdx.z * M_ * M_;
    } else {
        Ap = g_ot;
        W  = g_wtf + (size_t)3 * M_ * M_;
    }

    const int tid  = threadIdx.x;
    const int lane = tid & 31;
    const int wid  = tid >> 5;
    const int wm   = wid & 1;
    const int wn   = wid >> 1;
    const int g    = lane >> 2;
    const int lq   = lane & 3;

    const int r0 = blockIdx.y * 128;
    const int c0 = blockIdx.x * 128;

    const uint32_t smbase = (uint32_t)__cvta_generic_to_shared(smw);

    auto issue = [&](int c) {
        const int s = c % 3;
        const uint32_t aB = smbase + s * STG_WORDS * 4;
        const uint32_t bB = aB + AS_WORDS * 4;
        const int kc = c * 32;
#pragma unroll
        for (int it = 0; it < 4; it++) {
            int idx = tid + it * 256;
            int r = idx >> 3, k4 = idx & 7;
            cp16(aB + (r * AP + 4 * k4) * 4,
                 Ap + (size_t)(r0 + r) * 1024 + kc + 4 * k4);
            int k = idx >> 5, n4 = idx & 31;
            cp16(bB + (k * BP + 4 * n4) * 4,
                 W + (size_t)(kc + k) * 1024 + c0 + 4 * n4);
        }
        CP_COMMIT();
    };

    float acc[4][4][4];
#pragma unroll
    for (int i = 0; i < 4; i++)
#pragma unroll
        for (int j = 0; j < 4; j++)
#pragma unroll
            for (int e = 0; e < 4; e++) acc[i][j][e] = 0.0f;

    issue(0);
    issue(1);

    for (int c = 0; c < 32; c++) {
        if (c < 30) { CP_WAIT(1); } else { CP_WAIT(0); }
        __syncthreads();

        const uint32_t* As = smw + (c % 3) * STG_WORDS;
        const uint32_t* Bs = As + AS_WORDS;

#pragma unroll
        for (int ks = 0; ks < 4; ks++) {
            const int kk = ks * 8;
            uint32_t afr[4][4];
#pragma unroll
            for (int mf = 0; mf < 4; mf++) {
                const uint32_t* p = &As[(wm * 64 + mf * 16 + g) * AP + kk + lq];
                afr[mf][0] = p[0];
                afr[mf][1] = p[8 * AP];
                afr[mf][2] = p[4];
                afr[mf][3] = p[8 * AP + 4];
            }
            uint32_t bfr[4][2];
#pragma unroll
            for (int nf = 0; nf < 4; nf++) {
                const uint32_t* p = &Bs[(kk + lq) * BP + wn * 32 + nf * 8 + g];
                bfr[nf][0] = p[0];
                bfr[nf][1] = p[4 * BP];
            }
#pragma unroll
            for (int mf = 0; mf < 4; mf++)
#pragma unroll
                for (int nf = 0; nf < 4; nf++)
                    mma_tf32(acc[mf][nf], afr[mf], bfr[nf]);
        }

        if (c + 2 < 32) issue(c + 2);
    }

    // ---- epilogue ----
#pragma unroll
    for (int mf = 0; mf < 4; mf++) {
#pragma unroll
        for (int half = 0; half < 2; half++) {
            int row = r0 + wm * 64 + mf * 16 + g + half * 8;
#pragma unroll
            for (int nf = 0; nf < 4; nf++) {
                int col = wn * 32 + nf * 8 + 2 * lq;
                float v0 = half ? acc[mf][nf][2] : acc[mf][nf][0];
                float v1 = half ? acc[mf][nf][3] : acc[mf][nf][1];
                if (MODE == 0) {
                    int bb = row >> 11, t = row & 2047;
                    size_t off = ((size_t)(bb * H_ + blockIdx.x) * T_ + t) * D_ + col;
                    if (blockIdx.z == 2) {
                        *(uint2*)(g_vt + off) = make_uint2(f2tf(v0), f2tf(v1));
                    } else {
                        float* O = (blockIdx.z == 0) ? g_q : g_k;
                        *(float2*)(O + off) = make_float2(v0, v1);
                    }
                } else {
                    *(float2*)(Cout + (size_t)row * 1024 + c0 + col) =
                        make_float2(v0, v1);
                }
            }
        }
    }
}

// ---------------------------------------------------------------------------
// Fractional RoPE: read f32 g_q/g_k, write FULL tf32 rows to g_qt/g_kt.
// 64 threads: tid<32 -> q, else k; each thread d in [0,32):
// rotate (d, d+32), passthrough copy (d+64, d+96).
// ---------------------------------------------------------------------------
__global__ void rope_kernel()
{
    const int t  = blockIdx.x;
    const int bh = blockIdx.y;
    const int d  = threadIdx.x & 31;
    const bool isq = (threadIdx.x < 32);
    const size_t off = ((size_t)bh * T_ + t) * D_;
    const float* src = (isq ? g_q : g_k) + off;
    uint32_t* dst = (isq ? g_qt : g_kt) + off;

    float freq = powf(10000.0f, -(float)d * (1.0f / 32.0f));
    float rad  = (float)t * freq;
    float sn, cs;
    sincosf(rad, &sn, &cs);
    float e = src[d], o = src[d + 32];
    dst[d]      = f2tf(e * cs - o * sn);
    dst[d + 32] = f2tf(e * sn + o * cs);
    dst[d + 64] = f2tf(src[d + 64]);
    dst[d + 96] = f2tf(src[d + 96]);
}

// ---------------------------------------------------------------------------
// Tensor-core flash attention (causal, scale 1/128), tf32 mma.sync.
// Br=64, Bc=64, 4 warps; Q reg-resident; K row-major smem pitch 132
// (frag bank 4g+lq, conflict-free); all tiles loaded via cp.async from
// pre-converted tf32 gmem. exp2-domain online softmax. Reverse qblk order.
// ---------------------------------------------------------------------------
#define KSP 132
#define VSP 136
#define PSP 72
#define KQ_WORDS (64 * KSP)                                    // 8448
#define ATTN_SMEM_BYTES ((KQ_WORDS + 64 * VSP + 64 * PSP) * 4) // 87296

__global__ void __launch_bounds__(128) attn_mma()
{
    extern __shared__ uint32_t smu[];
    uint32_t* KQ = smu;                      // Q stage then K tiles [64][132]
    uint32_t* Vs = smu + KQ_WORDS;           // [64][136]
    uint32_t* Ps = Vs + 64 * VSP;            // [64][72]

    const int qblk = gridDim.x - 1 - blockIdx.x;   // longest first
    const int bh   = blockIdx.y;
    const uint32_t* Qg = g_qt + (size_t)bh * T_ * D_ + (size_t)qblk * 64 * D_;
    const uint32_t* Kg = g_kt + (size_t)bh * T_ * D_;
    const uint32_t* Vg = g_vt + (size_t)bh * T_ * D_;

    const int tid  = threadIdx.x;
    const int lane = tid & 31;
    const int wr   = tid >> 5;
    const int g    = lane >> 2;
    const int lq   = lane & 3;

    const uint32_t kqB = (uint32_t)__cvta_generic_to_shared(KQ);
    const uint32_t vsB = (uint32_t)__cvta_generic_to_shared(Vs);

    // ---- stage Q via cp.async ----
#pragma unroll
    for (int it = 0; it < 16; it++) {
        int idx = tid + it * 128;
        int r = idx >> 5, d4 = idx & 31;
        cp16(kqB + (r * KSP + 4 * d4) * 4, Qg + (size_t)r * D_ + 4 * d4);
    }
    CP_COMMIT();
    CP_WAIT(0);
    __syncthreads();

    uint32_t qfr[16][4];
#pragma unroll
    for (int ks = 0; ks < 16; ks++) {
        const uint32_t* p = &KQ[(wr * 16 + g) * KSP + 8 * ks + lq];
        qfr[ks][0] = p[0];
        qfr[ks][1] = p[8 * KSP];
        qfr[ks][2] = p[4];
        qfr[ks][3] = p[8 * KSP + 4];
    }

    float oacc[16][4];
#pragma unroll
    for (int nf = 0; nf < 16; nf++)
#pragma unroll
        for (int e = 0; e < 4; e++) oacc[nf][e] = 0.0f;
    float mrow[2] = { -1e30f, -1e30f };
    float lrow[2] = { 0.0f, 0.0f };

    const float Kc = 1.44269504f / 128.0f;

    for (int jt = 0; jt <= qblk; jt++) {
        __syncthreads();   // all warps done with previous K/V

        // K + V tiles via cp.async (row-major tf32)
#pragma unroll
        for (int it = 0; it < 16; it++) {
            int idx = tid + it * 128;
            int r = idx >> 5, d4 = idx & 31;
            cp16(kqB + (r * KSP + 4 * d4) * 4,
                 Kg + (size_t)(jt * 64 + r) * D_ + 4 * d4);
            cp16(vsB + (r * VSP + 4 * d4) * 4,
                 Vg + (size_t)(jt * 64 + r) * D_ + 4 * d4);
        }
        CP_COMMIT();
        CP_WAIT(0);
        __syncthreads();

        // ---- S = Q K^T ----
        float sacc[8][4];
#pragma unroll
        for (int nf = 0; nf < 8; nf++)
#pragma unroll
            for (int e = 0; e < 4; e++) sacc[nf][e] = 0.0f;

#pragma unroll
        for (int ks = 0; ks < 16; ks++) {
            uint32_t bfr[8][2];
#pragma unroll
            for (int nf = 0; nf < 8; nf++) {
                const uint32_t* p = &KQ[(8 * nf + g) * KSP + 8 * ks + lq];
                bfr[nf][0] = p[0];
                bfr[nf][1] = p[4];
            }
#pragma unroll
            for (int nf = 0; nf < 8; nf++)
                mma_tf32(sacc[nf], qfr[ks], bfr[nf]);
        }

#pragma unroll
        for (int nf = 0; nf < 8; nf++)
#pragma unroll
            for (int e = 0; e < 4; e++) sacc[nf][e] *= Kc;

        if (jt == qblk) {
#pragma unroll
            for (int nf = 0; nf < 8; nf++)
#pragma unroll
                for (int e = 0; e < 4; e++) {
                    int col = nf * 8 + 2 * lq + (e & 1);
                    int row = wr * 16 + g + (e >> 1) * 8;
                    if (col > row) sacc[nf][e] = -1e30f;
                }
        }

        float zmax[2] = { -1e30f, -1e30f };
#pragma unroll
        for (int nf = 0; nf < 8; nf++) {
            zmax[0] = fmaxf(zmax[0], fmaxf(sacc[nf][0], sacc[nf][1]));
            zmax[1] = fmaxf(zmax[1], fmaxf(sacc[nf][2], sacc[nf][3]));
        }
#pragma unroll
        for (int off = 1; off <= 2; off <<= 1) {
            zmax[0] = fmaxf(zmax[0], __shfl_xor_sync(0xffffffffu, zmax[0], off));
            zmax[1] = fmaxf(zmax[1], __shfl_xor_sync(0xffffffffu, zmax[1], off));
        }

        float alpha[2], psum[2] = { 0.0f, 0.0f };
#pragma unroll
        for (int rr = 0; rr < 2; rr++) {
            float mn = fmaxf(mrow[rr], zmax[rr]);
            alpha[rr] = ex2(mrow[rr] - mn);
            mrow[rr] = mn;
        }
#pragma unroll
        for (int nf = 0; nf < 8; nf++) {
            float p0 = ex2(sacc[nf][0] - mrow[0]);
            float p1 = ex2(sacc[nf][1] - mrow[0]);
            float p2 = ex2(sacc[nf][2] - mrow[1]);
            float p3 = ex2(sacc[nf][3] - mrow[1]);
            sacc[nf][0] = p0; sacc[nf][1] = p1;
            sacc[nf][2] = p2; sacc[nf][3] = p3;
            psum[0] += p0 + p1;
            psum[1] += p2 + p3;
        }
#pragma unroll
        for (int off = 1; off <= 2; off <<= 1) {
            psum[0] += __shfl_xor_sync(0xffffffffu, psum[0], off);
            psum[1] += __shfl_xor_sync(0xffffffffu, psum[1], off);
        }
        lrow[0] = lrow[0] * alpha[0] + psum[0];
        lrow[1] = lrow[1] * alpha[1] + psum[1];
#pragma unroll
        for (int nf = 0; nf < 16; nf++) {
            oacc[nf][0] *= alpha[0]; oacc[nf][1] *= alpha[0];
            oacc[nf][2] *= alpha[1]; oacc[nf][3] *= alpha[1];
        }

        // ---- P -> smem (tf32), warp-private region ----
#pragma unroll
        for (int nf = 0; nf < 8; nf++) {
            uint2 u0 = make_uint2(f2tf(sacc[nf][0]), f2tf(sacc[nf][1]));
            uint2 u1 = make_uint2(f2tf(sacc[nf][2]), f2tf(sacc[nf][3]));
            *(uint2*)&Ps[(wr * 16 + g) * PSP + 8 * nf + 2 * lq] = u0;
            *(uint2*)&Ps[(wr * 16 + g + 8) * PSP + 8 * nf + 2 * lq] = u1;
        }
        __syncwarp();

        // ---- O += P V ----
#pragma unroll
        for (int ks = 0; ks < 8; ks++) {
            uint32_t pfr[4];
            const uint32_t* pp = &Ps[(wr * 16 + g) * PSP + 8 * ks + lq];
            pfr[0] = pp[0];
            pfr[1] = pp[8 * PSP];
            pfr[2] = pp[4];
            pfr[3] = pp[8 * PSP + 4];
#pragma unroll
            for (int nf = 0; nf < 16; nf++) {
                uint32_t vfr[2];
                const uint32_t* vp = &Vs[(8 * ks + lq) * VSP + 8 * nf + g];
                vfr[0] = vp[0];
                vfr[1] = vp[4 * VSP];
                mma_tf32(oacc[nf], pfr, vfr);
            }
        }
    }

    // ---- epilogue: normalize, write tf32 into g_ot [B,T,H*D] ----
    const int b = bh >> 3, h = bh & 7;
    const float invl0 = 1.0f / lrow[0];
    const float invl1 = 1.0f / lrow[1];
    const int t0 = qblk * 64 + wr * 16 + g;
    uint32_t* dst0 = g_ot + ((size_t)(b * T_ + t0) * H_ + h) * D_;
    uint32_t* dst1 = g_ot + ((size_t)(b * T_ + t0 + 8) * H_ + h) * D_;
#pragma unroll
    for (int nf = 0; nf < 16; nf++) {
        int col = 8 * nf + 2 * lq;
        *(uint2*)(dst0 + col) = make_uint2(f2tf(oacc[nf][0] * invl0),
                                           f2tf(oacc[nf][1] * invl0));
        *(uint2*)(dst1 + col) = make_uint2(f2tf(oacc[nf][2] * invl1),
                                           f2tf(oacc[nf][3] * invl1));
    }
}

// ---------------------------------------------------------------------------
extern "C" void kernel_launch(void* const* d_in, const int* in_sizes, int n_in,
                              void* d_out, int out_size)
{
    const float* x  = (const float*)d_in[0];
    const float* wq = (const float*)d_in[1];
    const float* wk = (const float*)d_in[2];
    const float* wv = (const float*)d_in[3];
    const float* wo = (const float*)d_in[4];
    float* out = (float*)d_out;

    cudaFuncSetAttribute(gemm_cp<0>,
                         cudaFuncAttributeMaxDynamicSharedMemorySize, GEMM_SMEM_BYTES);
    cudaFuncSetAttribute(gemm_cp<1>,
                         cudaFuncAttributeMaxDynamicSharedMemorySize, GEMM_SMEM_BYTES);
    cudaFuncSetAttribute(attn_mma,
                         cudaFuncAttributeMaxDynamicSharedMemorySize, ATTN_SMEM_BYTES);

    // tf32 pre-conversion of x and weights
    conv_x<<<4096, 256>>>(x);
    conv_w<<<dim3(1024, 4), 256>>>(wq, wk, wv, wo);

    // QKV projection (q,k -> f32; v -> tf32)
    gemm_cp<0><<<dim3(8, 32, 3), 256, GEMM_SMEM_BYTES>>>(nullptr);

    // Fractional RoPE: q,k -> tf32 g_qt/g_kt
    rope_kernel<<<dim3(T_, BH_), 64>>>();

    // Tensor-core flash attention (tf32 in, tf32 out)
    attn_mma<<<dim3(T_ / 64, BH_), 128, ATTN_SMEM_BYTES>>>();

    // Output projection
    gemm_cp<1><<<dim3(8, 32), 256, GEMM_SMEM_BYTES>>>(out);
}

// round 8
// speedup vs baseline: 4.0999x; 1.0107x over previous
#include <cuda_runtime.h>
#include <cstdint>
#include <math.h>

#define B_ 2
#define T_ 2048
#define M_ 1024
#define H_ 8
#define D_ 128
#define BH_ (B_*H_)

// Scratch (allocation-free: device globals)
__device__ float    g_q[BH_ * T_ * D_];        // [B,H,T,D] f32 (pre-rope)
__device__ float    g_k[BH_ * T_ * D_];        // [B,H,T,D] f32 (pre-rope)
__device__ uint32_t g_qt[BH_ * T_ * D_];       // tf32 q (post-rope)
__device__ uint32_t g_kt[BH_ * T_ * D_];       // tf32 k (post-rope)
__device__ uint32_t g_vt[BH_ * T_ * D_];       // tf32 v
__device__ uint32_t g_ot[B_ * T_ * H_ * D_];   // [B,T,H*D] tf32 (attention out)
__device__ uint32_t g_xt[B_ * T_ * M_];        // tf32(x)
__device__ uint32_t g_wtf[4 * M_ * M_];        // tf32(wq,wk,wv,wo)
__device__ float2   g_csn[T_ * 32];            // rope cos/sin table

__device__ __forceinline__ uint32_t f2tf(float x) {
    uint32_t r;
    asm("cvt.rna.tf32.f32 %0, %1;" : "=r"(r) : "f"(x));
    return r;
}
__device__ __forceinline__ float ex2(float x) {
    float r;
    asm("ex2.approx.ftz.f32 %0, %1;" : "=f"(r) : "f"(x));
    return r;
}
__device__ __forceinline__ void mma_tf32(float c[4], const uint32_t a[4],
                                         const uint32_t b[2]) {
    asm volatile(
        "mma.sync.aligned.m16n8k8.row.col.f32.tf32.tf32.f32 "
        "{%0,%1,%2,%3}, {%4,%5,%6,%7}, {%8,%9}, {%0,%1,%2,%3};"
        : "+f"(c[0]), "+f"(c[1]), "+f"(c[2]), "+f"(c[3])
        : "r"(a[0]), "r"(a[1]), "r"(a[2]), "r"(a[3]), "r"(b[0]), "r"(b[1]));
}
__device__ __forceinline__ void cp16(uint32_t smem_dst, const void* gptr) {
    asm volatile("cp.async.cg.shared.global [%0], [%1], 16;"
                 :: "r"(smem_dst), "l"(gptr));
}
#define CP_COMMIT() asm volatile("cp.async.commit_group;" ::: "memory")
#define CP_WAIT(n)  asm volatile("cp.async.wait_group %0;" :: "n"(n) : "memory")

// ---------------------------------------------------------------------------
// tf32 pre-conversion + rope table
// ---------------------------------------------------------------------------
__global__ void conv_x(const float* __restrict__ x)
{
    int i = blockIdx.x * 256 + threadIdx.x;
    float4 v = ((const float4*)x)[i];
    ((uint4*)g_xt)[i] = make_uint4(f2tf(v.x), f2tf(v.y), f2tf(v.z), f2tf(v.w));
}
__global__ void conv_w(const float* __restrict__ wq, const float* __restrict__ wk,
                       const float* __restrict__ wv, const float* __restrict__ wo)
{
    const float* src = (blockIdx.y == 0) ? wq : (blockIdx.y == 1) ? wk
                     : (blockIdx.y == 2) ? wv : wo;
    uint4* dst = (uint4*)(g_wtf + (size_t)blockIdx.y * M_ * M_);
    int i = blockIdx.x * 256 + threadIdx.x;
    float4 v = ((const float4*)src)[i];
    dst[i] = make_uint4(f2tf(v.x), f2tf(v.y), f2tf(v.z), f2tf(v.w));
}
__global__ void csn_kernel()
{
    int i = blockIdx.x * 256 + threadIdx.x;     // 65536 total
    int t = i >> 5, d = i & 31;
    float freq = powf(10000.0f, -(float)d * (1.0f / 32.0f));
    float sn, cs;
    sincosf((float)t * freq, &sn, &cs);
    g_csn[i] = make_float2(cs, sn);
}

// ---------------------------------------------------------------------------
// tf32 mma.sync GEMM with 3-stage cp.async pipeline (unchanged from R7).
// ---------------------------------------------------------------------------
#define AP 36
#define BP 136
#define AS_WORDS (128 * AP)
#define BS_WORDS (32 * BP)
#define STG_WORDS (AS_WORDS + BS_WORDS)
#define GEMM_SMEM_BYTES (3 * STG_WORDS * 4)    // 107520

template <int MODE>
__global__ void __launch_bounds__(256, 2) gemm_cp(float* __restrict__ Cout)
{
    extern __shared__ uint32_t smw[];

    const uint32_t* Ap;
    const uint32_t* W;
    if (MODE == 0) {
        Ap = g_xt;
        W  = g_wtf + (size_t)blockIdx.z * M_ * M_;
    } else {
        Ap = g_ot;
        W  = g_wtf + (size_t)3 * M_ * M_;
    }

    const int tid  = threadIdx.x;
    const int lane = tid & 31;
    const int wid  = tid >> 5;
    const int wm   = wid & 1;
    const int wn   = wid >> 1;
    const int g    = lane >> 2;
    const int lq   = lane & 3;

    const int r0 = blockIdx.y * 128;
    const int c0 = blockIdx.x * 128;

    const uint32_t smbase = (uint32_t)__cvta_generic_to_shared(smw);

    auto issue = [&](int c) {
        const int s = c % 3;
        const uint32_t aB = smbase + s * STG_WORDS * 4;
        const uint32_t bB = aB + AS_WORDS * 4;
        const int kc = c * 32;
#pragma unroll
        for (int it = 0; it < 4; it++) {
            int idx = tid + it * 256;
            int r = idx >> 3, k4 = idx & 7;
            cp16(aB + (r * AP + 4 * k4) * 4,
                 Ap + (size_t)(r0 + r) * 1024 + kc + 4 * k4);
            int k = idx >> 5, n4 = idx & 31;
            cp16(bB + (k * BP + 4 * n4) * 4,
                 W + (size_t)(kc + k) * 1024 + c0 + 4 * n4);
        }
        CP_COMMIT();
    };

    float acc[4][4][4];
#pragma unroll
    for (int i = 0; i < 4; i++)
#pragma unroll
        for (int j = 0; j < 4; j++)
#pragma unroll
            for (int e = 0; e < 4; e++) acc[i][j][e] = 0.0f;

    issue(0);
    issue(1);

    for (int c = 0; c < 32; c++) {
        if (c < 30) { CP_WAIT(1); } else { CP_WAIT(0); }
        __syncthreads();

        const uint32_t* As = smw + (c % 3) * STG_WORDS;
        const uint32_t* Bs = As + AS_WORDS;

#pragma unroll
        for (int ks = 0; ks < 4; ks++) {
            const int kk = ks * 8;
            uint32_t afr[4][4];
#pragma unroll
            for (int mf = 0; mf < 4; mf++) {
                const uint32_t* p = &As[(wm * 64 + mf * 16 + g) * AP + kk + lq];
                afr[mf][0] = p[0];
                afr[mf][1] = p[8 * AP];
                afr[mf][2] = p[4];
                afr[mf][3] = p[8 * AP + 4];
            }
            uint32_t bfr[4][2];
#pragma unroll
            for (int nf = 0; nf < 4; nf++) {
                const uint32_t* p = &Bs[(kk + lq) * BP + wn * 32 + nf * 8 + g];
                bfr[nf][0] = p[0];
                bfr[nf][1] = p[4 * BP];
            }
#pragma unroll
            for (int mf = 0; mf < 4; mf++)
#pragma unroll
                for (int nf = 0; nf < 4; nf++)
                    mma_tf32(acc[mf][nf], afr[mf], bfr[nf]);
        }

        if (c + 2 < 32) issue(c + 2);
    }

#pragma unroll
    for (int mf = 0; mf < 4; mf++) {
#pragma unroll
        for (int half = 0; half < 2; half++) {
            int row = r0 + wm * 64 + mf * 16 + g + half * 8;
#pragma unroll
            for (int nf = 0; nf < 4; nf++) {
                int col = wn * 32 + nf * 8 + 2 * lq;
                float v0 = half ? acc[mf][nf][2] : acc[mf][nf][0];
                float v1 = half ? acc[mf][nf][3] : acc[mf][nf][1];
                if (MODE == 0) {
                    int bb = row >> 11, t = row & 2047;
                    size_t off = ((size_t)(bb * H_ + blockIdx.x) * T_ + t) * D_ + col;
                    if (blockIdx.z == 2) {
                        *(uint2*)(g_vt + off) = make_uint2(f2tf(v0), f2tf(v1));
                    } else {
                        float* O = (blockIdx.z == 0) ? g_q : g_k;
                        *(float2*)(O + off) = make_float2(v0, v1);
                    }
                } else {
                    *(float2*)(Cout + (size_t)row * 1024 + c0 + col) =
                        make_float2(v0, v1);
                }
            }
        }
    }
}

// ---------------------------------------------------------------------------
// Fractional RoPE via precomputed table: memory-bound.
// 256 threads handle 4 t's; within 64-thread group: tid<32 -> q, else k.
// ---------------------------------------------------------------------------
__global__ void rope_kernel()
{
    const int t  = blockIdx.x * 4 + (threadIdx.x >> 6);
    const int bh = blockIdx.y;
    const int r  = threadIdx.x & 63;
    const int d  = r & 31;
    const bool isq = (r < 32);
    const size_t off = ((size_t)bh * T_ + t) * D_;
    const float* src = (isq ? g_q : g_k) + off;
    uint32_t* dst = (isq ? g_qt : g_kt) + off;

    float2 cssn = g_csn[t * 32 + d];
    float e = src[d], o = src[d + 32];
    dst[d]      = f2tf(e * cssn.x - o * cssn.y);
    dst[d + 32] = f2tf(e * cssn.y + o * cssn.x);
    dst[d + 64] = f2tf(src[d + 64]);
    dst[d + 96] = f2tf(src[d + 96]);
}

// ---------------------------------------------------------------------------
// Tensor-core flash attention, software-pipelined with split cp.async groups:
// K(jt+1) load overlaps softmax+PV(jt); V(jt+1) load overlaps S(jt+1).
// Br=Bc=64, 4 warps; Q reg-resident; exp2 online softmax; reverse qblk order.
// ---------------------------------------------------------------------------
#define KSP 132
#define VSP 136
#define PSP 72
#define KQ_WORDS (64 * KSP)
#define ATTN_SMEM_BYTES ((KQ_WORDS + 64 * VSP + 64 * PSP) * 4) // 87296

__global__ void __launch_bounds__(128) attn_mma()
{
    extern __shared__ uint32_t smu[];
    uint32_t* KQ = smu;                      // Q stage then K tiles [64][132]
    uint32_t* Vs = smu + KQ_WORDS;           // [64][136]
    uint32_t* Ps = Vs + 64 * VSP;            // [64][72]

    const int qblk = gridDim.x - 1 - blockIdx.x;   // longest first
    const int bh   = blockIdx.y;
    const uint32_t* Qg = g_qt + (size_t)bh * T_ * D_ + (size_t)qblk * 64 * D_;
    const uint32_t* Kg = g_kt + (size_t)bh * T_ * D_;
    const uint32_t* Vg = g_vt + (size_t)bh * T_ * D_;

    const int tid  = threadIdx.x;
    const int lane = tid & 31;
    const int wr   = tid >> 5;
    const int g    = lane >> 2;
    const int lq   = lane & 3;

    const uint32_t kqB = (uint32_t)__cvta_generic_to_shared(KQ);
    const uint32_t vsB = (uint32_t)__cvta_generic_to_shared(Vs);

    auto issueK = [&](int jt) {
#pragma unroll
        for (int it = 0; it < 16; it++) {
            int idx = tid + it * 128;
            int r = idx >> 5, d4 = idx & 31;
            cp16(kqB + (r * KSP + 4 * d4) * 4,
                 Kg + (size_t)(jt * 64 + r) * D_ + 4 * d4);
        }
        CP_COMMIT();
    };
    auto issueV = [&](int jt) {
#pragma unroll
        for (int it = 0; it < 16; it++) {
            int idx = tid + it * 128;
            int r = idx >> 5, d4 = idx & 31;
            cp16(vsB + (r * VSP + 4 * d4) * 4,
                 Vg + (size_t)(jt * 64 + r) * D_ + 4 * d4);
        }
        CP_COMMIT();
    };

    // ---- stage Q, load register fragments ----
#pragma unroll
    for (int it = 0; it < 16; it++) {
        int idx = tid + it * 128;
        int r = idx >> 5, d4 = idx & 31;
        cp16(kqB + (r * KSP + 4 * d4) * 4, Qg + (size_t)r * D_ + 4 * d4);
    }
    CP_COMMIT();
    CP_WAIT(0);
    __syncthreads();

    uint32_t qfr[16][4];
#pragma unroll
    for (int ks = 0; ks < 16; ks++) {
        const uint32_t* p = &KQ[(wr * 16 + g) * KSP + 8 * ks + lq];
        qfr[ks][0] = p[0];
        qfr[ks][1] = p[8 * KSP];
        qfr[ks][2] = p[4];
        qfr[ks][3] = p[8 * KSP + 4];
    }
    __syncthreads();   // all warps done reading Q before K(0) overwrites

    issueK(0);
    issueV(0);
    CP_WAIT(0);
    __syncthreads();

    float oacc[16][4];
#pragma unroll
    for (int nf = 0; nf < 16; nf++)
#pragma unroll
        for (int e = 0; e < 4; e++) oacc[nf][e] = 0.0f;
    float mrow[2] = { -1e30f, -1e30f };
    float lrow[2] = { 0.0f, 0.0f };

    const float Kc = 1.44269504f / 128.0f;

    for (int jt = 0; jt <= qblk; jt++) {
        // invariant: K(jt) visible; V(jt) is oldest pending group (or visible)

        // ---- S = Q K^T ----
        float sacc[8][4];
#pragma unroll
        for (int nf = 0; nf < 8; nf++)
#pragma unroll
            for (int e = 0; e < 4; e++) sacc[nf][e] = 0.0f;

#pragma unroll
        for (int ks = 0; ks < 16; ks++) {
            uint32_t bfr[8][2];
#pragma unroll
            for (int nf = 0; nf < 8; nf++) {
                const uint32_t* p = &KQ[(8 * nf + g) * KSP + 8 * ks + lq];
                bfr[nf][0] = p[0];
                bfr[nf][1] = p[4];
            }
#pragma unroll
            for (int nf = 0; nf < 8; nf++)
                mma_tf32(sacc[nf], qfr[ks], bfr[nf]);
        }

        __syncthreads();                 // all warps done reading K(jt)
        if (jt < qblk) issueK(jt + 1);   // overlaps softmax + PV

        // ---- softmax (exp2 domain) ----
#pragma unroll
        for (int nf = 0; nf < 8; nf++)
#pragma unroll
            for (int e = 0; e < 4; e++) sacc[nf][e] *= Kc;

        if (jt == qblk) {
#pragma unroll
            for (int nf = 0; nf < 8; nf++)
#pragma unroll
                for (int e = 0; e < 4; e++) {
                    int col = nf * 8 + 2 * lq + (e & 1);
                    int row = wr * 16 + g + (e >> 1) * 8;
                    if (col > row) sacc[nf][e] = -1e30f;
                }
        }

        float zmax[2] = { -1e30f, -1e30f };
#pragma unroll
        for (int nf = 0; nf < 8; nf++) {
            zmax[0] = fmaxf(zmax[0], fmaxf(sacc[nf][0], sacc[nf][1]));
            zmax[1] = fmaxf(zmax[1], fmaxf(sacc[nf][2], sacc[nf][3]));
        }
#pragma unroll
        for (int off = 1; off <= 2; off <<= 1) {
            zmax[0] = fmaxf(zmax[0], __shfl_xor_sync(0xffffffffu, zmax[0], off));
            zmax[1] = fmaxf(zmax[1], __shfl_xor_sync(0xffffffffu, zmax[1], off));
        }

        float alpha[2], psum[2] = { 0.0f, 0.0f };
#pragma unroll
        for (int rr = 0; rr < 2; rr++) {
            float mn = fmaxf(mrow[rr], zmax[rr]);
            alpha[rr] = ex2(mrow[rr] - mn);
            mrow[rr] = mn;
        }
#pragma unroll
        for (int nf = 0; nf < 8; nf++) {
            float p0 = ex2(sacc[nf][0] - mrow[0]);
            float p1 = ex2(sacc[nf][1] - mrow[0]);
            float p2 = ex2(sacc[nf][2] - mrow[1]);
            float p3 = ex2(sacc[nf][3] - mrow[1]);
            sacc[nf][0] = p0; sacc[nf][1] = p1;
            sacc[nf][2] = p2; sacc[nf][3] = p3;
            psum[0] += p0 + p1;
            psum[1] += p2 + p3;
        }
#pragma unroll
        for (int off = 1; off <= 2; off <<= 1) {
            psum[0] += __shfl_xor_sync(0xffffffffu, psum[0], off);
            psum[1] += __shfl_xor_sync(0xffffffffu, psum[1], off);
        }
        lrow[0] = lrow[0] * alpha[0] + psum[0];
        lrow[1] = lrow[1] * alpha[1] + psum[1];
#pragma unroll
        for (int nf = 0; nf < 16; nf++) {
            oacc[nf][0] *= alpha[0]; oacc[nf][1] *= alpha[0];
            oacc[nf][2] *= alpha[1]; oacc[nf][3] *= alpha[1];
        }

        // ---- P -> smem (warp-private) ----
#pragma unroll
        for (int nf = 0; nf < 8; nf++) {
            uint2 u0 = make_uint2(f2tf(sacc[nf][0]), f2tf(sacc[nf][1]));
            uint2 u1 = make_uint2(f2tf(sacc[nf][2]), f2tf(sacc[nf][3]));
            *(uint2*)&Ps[(wr * 16 + g) * PSP + 8 * nf + 2 * lq] = u0;
            *(uint2*)&Ps[(wr * 16 + g + 8) * PSP + 8 * nf + 2 * lq] = u1;
        }
        __syncwarp();

        // ---- ensure V(jt) visible (drain older group) ----
        if (jt < qblk) { CP_WAIT(1); } else { CP_WAIT(0); }
        __syncthreads();

        // ---- O += P V ----
#pragma unroll
        for (int ks = 0; ks < 8; ks++) {
            uint32_t pfr[4];
            const uint32_t* pp = &Ps[(wr * 16 + g) * PSP + 8 * ks + lq];
            pfr[0] = pp[0];
            pfr[1] = pp[8 * PSP];
            pfr[2] = pp[4];
            pfr[3] = pp[8 * PSP + 4];
#pragma unroll
            for (int nf = 0; nf < 16; nf++) {
                uint32_t vfr[2];
                const uint32_t* vp = &Vs[(8 * ks + lq) * VSP + 8 * nf + g];
                vfr[0] = vp[0];
                vfr[1] = vp[4 * VSP];
                mma_tf32(oacc[nf], pfr, vfr);
            }
        }

        __syncthreads();                 // all warps done reading V(jt)
        if (jt < qblk) {
            issueV(jt + 1);              // overlaps S(jt+1)
            CP_WAIT(1);                  // K(jt+1) complete
        }
        __syncthreads();                 // K(jt+1) visible to all warps
    }

    // ---- epilogue: normalize, write tf32 into g_ot [B,T,H*D] ----
    const int b = bh >> 3, h = bh & 7;
    const float invl0 = 1.0f / lrow[0];
    const float invl1 = 1.0f / lrow[1];
    const int t0 = qblk * 64 + wr * 16 + g;
    uint32_t* dst0 = g_ot + ((size_t)(b * T_ + t0) * H_ + h) * D_;
    uint32_t* dst1 = g_ot + ((size_t)(b * T_ + t0 + 8) * H_ + h) * D_;
#pragma unroll
    for (int nf = 0; nf < 16; nf++) {
        int col = 8 * nf + 2 * lq;
        *(uint2*)(dst0 + col) = make_uint2(f2tf(oacc[nf][0] * invl0),
                                           f2tf(oacc[nf][1] * invl0));
        *(uint2*)(dst1 + col) = make_uint2(f2tf(oacc[nf][2] * invl1),
                                           f2tf(oacc[nf][3] * invl1));
    }
}

// ---------------------------------------------------------------------------
extern "C" void kernel_launch(void* const* d_in, const int* in_sizes, int n_in,
                              void* d_out, int out_size)
{
    const float* x  = (const float*)d_in[0];
    const float* wq = (const float*)d_in[1];
    const float* wk = (const float*)d_in[2];
    const float* wv = (const float*)d_in[3];
    const float* wo = (const float*)d_in[4];
    float* out = (float*)d_out;

    cudaFuncSetAttribute(gemm_cp<0>,
                         cudaFuncAttributeMaxDynamicSharedMemorySize, GEMM_SMEM_BYTES);
    cudaFuncSetAttribute(gemm_cp<1>,
                         cudaFuncAttributeMaxDynamicSharedMemorySize, GEMM_SMEM_BYTES);
    cudaFuncSetAttribute(attn_mma,
                         cudaFuncAttributeMaxDynamicSharedMemorySize, ATTN_SMEM_BYTES);

    // tf32 pre-conversion + rope table
    conv_x<<<4096, 256>>>(x);
    conv_w<<<dim3(1024, 4), 256>>>(wq, wk, wv, wo);
    csn_kernel<<<256, 256>>>();

    // QKV projection (q,k -> f32; v -> tf32)
    gemm_cp<0><<<dim3(8, 32, 3), 256, GEMM_SMEM_BYTES>>>(nullptr);

    // Fractional RoPE (table-based): q,k -> tf32 g_qt/g_kt
    rope_kernel<<<dim3(T_ / 4, BH_), 256>>>();

    // Tensor-core flash attention (pipelined)
    attn_mma<<<dim3(T_ / 64, BH_), 128, ATTN_SMEM_BYTES>>>();

    // Output projection
    gemm_cp<1><<<dim3(8, 32), 256, GEMM_SMEM_BYTES>>>(out);
}